// round 1
// baseline (speedup 1.0000x reference)
#include <cuda_runtime.h>
#include <math.h>

#define NB 16
#define NC 128
#define NL 256
#define ND 512
#define ROWS (NB*NC)   // 2048

// ---------------- scratch (no allocations allowed) ----------------
__device__ float g_E0[ROWS*ND];
__device__ float g_total[ROWS];
__device__ float g_QKV[ROWS*3*ND];
__device__ float g_ctx[ROWS*ND];
__device__ float g_R1[ROWS*ND];
__device__ float g_E1[ROWS*ND];
__device__ float g_H[ROWS*2*ND];
__device__ float g_R2[ROWS*ND];

// ---------------- masked mean pool: E0[row,:] = sum_l x*m / max(sum m,1) ----
__global__ void pool_kernel(const float* __restrict__ x,
                            const float* __restrict__ mask) {
    const int row = blockIdx.x;           // b*NC + c
    const int tid = threadIdx.x;          // 128 threads
    __shared__ float msh[NL];
    __shared__ float red[128];

    float m0 = mask[(size_t)row*NL + tid];
    float m1 = mask[(size_t)row*NL + 128 + tid];
    msh[tid] = m0; msh[tid + 128] = m1;
    red[tid] = m0 + m1;
    __syncthreads();
    #pragma unroll
    for (int s = 64; s > 0; s >>= 1) {
        if (tid < s) red[tid] += red[tid + s];
        __syncthreads();
    }
    const float msum = red[0];

    const float4* xr = reinterpret_cast<const float4*>(x) + (size_t)row*NL*(ND/4);
    float4 acc = make_float4(0.f,0.f,0.f,0.f);
    #pragma unroll 4
    for (int l = 0; l < NL; l++) {
        float4 v = xr[(size_t)l*(ND/4) + tid];
        float m = msh[l];
        acc.x += v.x*m; acc.y += v.y*m; acc.z += v.z*m; acc.w += v.w*m;
    }
    const float inv = 1.0f / fmaxf(msum, 1.0f);
    acc.x *= inv; acc.y *= inv; acc.z *= inv; acc.w *= inv;
    reinterpret_cast<float4*>(g_E0)[(size_t)row*(ND/4) + tid] = acc;
    if (tid == 0) g_total[row] = msum;
}

// ---------------- SGEMM: C[M,N] = A[M,K] @ B[K,N] + bias (+Res) (+GELU) ----
// BM=BN=128, BK=8, TM=TN=8, 256 threads. All dims multiples of tile sizes.
#define EPI_BIAS 0
#define EPI_RES  1
#define EPI_GELU 2

__device__ __forceinline__ float gelu_exact(float v) {
    return 0.5f * v * (1.0f + erff(v * 0.70710678118654752f));
}

template<int EPI>
__global__ __launch_bounds__(256)
void sgemm128(const float* __restrict__ A, const float* __restrict__ B,
              const float* __restrict__ bias, const float* __restrict__ Res,
              float* __restrict__ C, int M, int N, int K) {
    __shared__ float As[8][128];
    __shared__ float Bs[8][128];

    const int tid = threadIdx.x;
    const int tr = tid >> 4;           // 0..15
    const int tc = tid & 15;           // 0..15
    const int aRow = tid >> 1;         // 0..127
    const int aCol = (tid & 1) * 4;    // 0 or 4
    const int bRow = tid >> 5;         // 0..7
    const int bCol = (tid & 31) * 4;   // 0..124

    const float* Ab = A + (size_t)blockIdx.y * 128 * K;
    const float* Bb = B + (size_t)blockIdx.x * 128;

    float acc[8][8];
    #pragma unroll
    for (int i = 0; i < 8; i++)
        #pragma unroll
        for (int j = 0; j < 8; j++) acc[i][j] = 0.f;

    for (int k0 = 0; k0 < K; k0 += 8) {
        float4 a4 = *reinterpret_cast<const float4*>(Ab + (size_t)aRow*K + k0 + aCol);
        As[aCol+0][aRow] = a4.x; As[aCol+1][aRow] = a4.y;
        As[aCol+2][aRow] = a4.z; As[aCol+3][aRow] = a4.w;
        float4 b4 = *reinterpret_cast<const float4*>(Bb + (size_t)(k0 + bRow)*N + bCol);
        *reinterpret_cast<float4*>(&Bs[bRow][bCol]) = b4;
        __syncthreads();
        #pragma unroll
        for (int kk = 0; kk < 8; kk++) {
            float ar[8], br[8];
            #pragma unroll
            for (int i = 0; i < 8; i++) ar[i] = As[kk][tr*8 + i];
            #pragma unroll
            for (int j = 0; j < 8; j++) br[j] = Bs[kk][tc*8 + j];
            #pragma unroll
            for (int i = 0; i < 8; i++)
                #pragma unroll
                for (int j = 0; j < 8; j++)
                    acc[i][j] += ar[i] * br[j];
        }
        __syncthreads();
    }

    const int crow0 = blockIdx.y * 128 + tr * 8;
    const int ccol0 = blockIdx.x * 128 + tc * 8;
    #pragma unroll
    for (int i = 0; i < 8; i++) {
        const int row = crow0 + i;
        #pragma unroll
        for (int j = 0; j < 8; j += 4) {
            const int col = ccol0 + j;
            float4 bv = *reinterpret_cast<const float4*>(bias + col);
            float4 r;
            r.x = acc[i][j+0] + bv.x;
            r.y = acc[i][j+1] + bv.y;
            r.z = acc[i][j+2] + bv.z;
            r.w = acc[i][j+3] + bv.w;
            if (EPI == EPI_RES) {
                float4 rv = *reinterpret_cast<const float4*>(Res + (size_t)row*N + col);
                r.x += rv.x; r.y += rv.y; r.z += rv.z; r.w += rv.w;
            }
            if (EPI == EPI_GELU) {
                r.x = gelu_exact(r.x); r.y = gelu_exact(r.y);
                r.z = gelu_exact(r.z); r.w = gelu_exact(r.w);
            }
            *reinterpret_cast<float4*>(C + (size_t)row*N + col) = r;
        }
    }
}

// ---------------- fused attention: scores + overlap + softmax + A@V --------
// grid: (NC/8, NB); block: 128 threads. Thread e owns key/value row e.
__global__ __launch_bounds__(128)
void attn_kernel(const float* __restrict__ mask) {
    const int b  = blockIdx.y;
    const int c0 = blockIdx.x * 8;
    const int e  = threadIdx.x;   // 0..127

    __shared__ float q_sh[8][ND];
    __shared__ float m_sh[8][NL];
    __shared__ float A_sh[8][NC];
    __shared__ float t_sh[8];
    __shared__ float rowmax[8], rowinv[8];

    #pragma unroll
    for (int j = 0; j < 8; j++) {
        const size_t qrow = (size_t)(b*NC + c0 + j);
        float4 qv = *reinterpret_cast<const float4*>(g_QKV + qrow*3*ND + e*4);
        *reinterpret_cast<float4*>(&q_sh[j][e*4]) = qv;
        if (e < 64) {
            float4 mv = *reinterpret_cast<const float4*>(mask + qrow*NL + e*4);
            *reinterpret_cast<float4*>(&m_sh[j][e*4]) = mv;
        }
    }
    if (e < 8) t_sh[e] = g_total[b*NC + c0 + e];
    __syncthreads();

    // S[j][e] = q_j . k_e
    const float* krow = g_QKV + (size_t)(b*NC + e)*3*ND + ND;
    float acc[8];
    #pragma unroll
    for (int j = 0; j < 8; j++) acc[j] = 0.f;
    for (int kk = 0; kk < ND; kk += 4) {
        float4 kv = *reinterpret_cast<const float4*>(krow + kk);
        #pragma unroll
        for (int j = 0; j < 8; j++) {
            float4 q4 = *reinterpret_cast<const float4*>(&q_sh[j][kk]);
            acc[j] += q4.x*kv.x + q4.y*kv.y + q4.z*kv.z + q4.w*kv.w;
        }
    }

    // joint[j][e] = mask_j . mask_e
    const float* mrow = mask + (size_t)(b*NC + e)*NL;
    float jacc[8];
    #pragma unroll
    for (int j = 0; j < 8; j++) jacc[j] = 0.f;
    for (int kk = 0; kk < NL; kk += 4) {
        float4 mv = *reinterpret_cast<const float4*>(mrow + kk);
        #pragma unroll
        for (int j = 0; j < 8; j++) {
            float4 m4 = *reinterpret_cast<const float4*>(&m_sh[j][kk]);
            jacc[j] += m4.x*mv.x + m4.y*mv.y + m4.z*mv.z + m4.w*mv.w;
        }
    }

    const float te = g_total[b*NC + e];
    float s[8];
    #pragma unroll
    for (int j = 0; j < 8; j++) {
        float tp = t_sh[j] + te;
        float ov = 2.0f * jacc[j] / fmaxf(tp, 1.0f);
        s[j] = acc[j] * 0.04419417382415922f * (0.5f + 0.5f * ov);
        A_sh[j][e] = s[j];
    }
    __syncthreads();

    if (e < 8) {
        float mx = -1e30f;
        for (int i = 0; i < NC; i++) mx = fmaxf(mx, A_sh[e][i]);
        float sm = 0.f;
        for (int i = 0; i < NC; i++) sm += expf(A_sh[e][i] - mx);
        rowmax[e] = mx; rowinv[e] = 1.0f / sm;
    }
    __syncthreads();

    #pragma unroll
    for (int j = 0; j < 8; j++)
        A_sh[j][e] = expf(s[j] - rowmax[j]) * rowinv[j];
    __syncthreads();

    // ctx[j][:] = sum_e A[j][e] * v[e][:], thread e handles cols [4e,4e+4)
    float4 o[8];
    #pragma unroll
    for (int j = 0; j < 8; j++) o[j] = make_float4(0.f,0.f,0.f,0.f);
    for (int ee = 0; ee < NC; ee++) {
        float4 v4 = *reinterpret_cast<const float4*>(
            g_QKV + (size_t)(b*NC + ee)*3*ND + 2*ND + e*4);
        #pragma unroll
        for (int j = 0; j < 8; j++) {
            float a = A_sh[j][ee];
            o[j].x += a*v4.x; o[j].y += a*v4.y; o[j].z += a*v4.z; o[j].w += a*v4.w;
        }
    }
    #pragma unroll
    for (int j = 0; j < 8; j++) {
        *reinterpret_cast<float4*>(g_ctx + (size_t)(b*NC + c0 + j)*ND + e*4) = o[j];
    }
}

// ---------------- LayerNorm over d=512, one block per row ------------------
__global__ __launch_bounds__(128)
void ln_kernel(const float* __restrict__ R, const float* __restrict__ g,
               const float* __restrict__ be, float* __restrict__ out) {
    const int row = blockIdx.x;
    const int tid = threadIdx.x;   // 128
    __shared__ float red_s[128];
    __shared__ float red_q[128];

    float4 v = reinterpret_cast<const float4*>(R)[(size_t)row*(ND/4) + tid];
    float s  = v.x + v.y + v.z + v.w;
    float sq = v.x*v.x + v.y*v.y + v.z*v.z + v.w*v.w;
    red_s[tid] = s; red_q[tid] = sq;
    __syncthreads();
    #pragma unroll
    for (int st = 64; st > 0; st >>= 1) {
        if (tid < st) { red_s[tid] += red_s[tid+st]; red_q[tid] += red_q[tid+st]; }
        __syncthreads();
    }
    const float mean = red_s[0] * (1.0f/ND);
    const float var  = red_q[0] * (1.0f/ND) - mean*mean;
    const float inv  = rsqrtf(var + 1e-5f);

    float4 g4 = reinterpret_cast<const float4*>(g)[tid];
    float4 b4 = reinterpret_cast<const float4*>(be)[tid];
    float4 r;
    r.x = (v.x - mean)*inv*g4.x + b4.x;
    r.y = (v.y - mean)*inv*g4.y + b4.y;
    r.z = (v.z - mean)*inv*g4.z + b4.z;
    r.w = (v.w - mean)*inv*g4.w + b4.w;
    reinterpret_cast<float4*>(out)[(size_t)row*(ND/4) + tid] = r;
}

// ---------------- launch ----------------------------------------------------
extern "C" void kernel_launch(void* const* d_in, const int* in_sizes, int n_in,
                              void* d_out, int out_size) {
    const float* x    = (const float*)d_in[0];
    const float* mask = (const float*)d_in[1];
    const float* Wqkv = (const float*)d_in[2];
    const float* bqkv = (const float*)d_in[3];
    const float* Wo   = (const float*)d_in[4];
    const float* bo   = (const float*)d_in[5];
    const float* W1   = (const float*)d_in[6];
    const float* b1   = (const float*)d_in[7];
    const float* W2   = (const float*)d_in[8];
    const float* b2   = (const float*)d_in[9];
    const float* g1   = (const float*)d_in[10];
    const float* be1  = (const float*)d_in[11];
    const float* g2   = (const float*)d_in[12];
    const float* be2  = (const float*)d_in[13];
    float* out = (float*)d_out;

    float *E0, *QKV, *ctx, *R1, *E1, *H, *R2;
    cudaGetSymbolAddress((void**)&E0,  g_E0);
    cudaGetSymbolAddress((void**)&QKV, g_QKV);
    cudaGetSymbolAddress((void**)&ctx, g_ctx);
    cudaGetSymbolAddress((void**)&R1,  g_R1);
    cudaGetSymbolAddress((void**)&E1,  g_E1);
    cudaGetSymbolAddress((void**)&H,   g_H);
    cudaGetSymbolAddress((void**)&R2,  g_R2);

    // 1) masked mean pool
    pool_kernel<<<ROWS, 128>>>(x, mask);

    // 2) QKV = E0 @ Wqkv + bqkv     (2048 x 1536 x 512)
    sgemm128<EPI_BIAS><<<dim3(3*ND/128, ROWS/128), 256>>>(E0, Wqkv, bqkv, nullptr, QKV, ROWS, 3*ND, ND);

    // 3) attention (scores, overlap, softmax, A@V)
    attn_kernel<<<dim3(NC/8, NB), 128>>>(mask);

    // 4) R1 = ctx @ Wo + bo + E0    (2048 x 512 x 512)
    sgemm128<EPI_RES><<<dim3(ND/128, ROWS/128), 256>>>(ctx, Wo, bo, E0, R1, ROWS, ND, ND);

    // 5) E1 = LN(R1)
    ln_kernel<<<ROWS, 128>>>(R1, g1, be1, E1);

    // 6) H = gelu(E1 @ W1 + b1)     (2048 x 1024 x 512)
    sgemm128<EPI_GELU><<<dim3(2*ND/128, ROWS/128), 256>>>(E1, W1, b1, nullptr, H, ROWS, 2*ND, ND);

    // 7) R2 = H @ W2 + b2 + E1      (2048 x 512 x 1024)
    sgemm128<EPI_RES><<<dim3(ND/128, ROWS/128), 256>>>(H, W2, b2, E1, R2, ROWS, ND, 2*ND);

    // 8) out = LN(R2)
    ln_kernel<<<ROWS, 128>>>(R2, g2, be2, out);
}

// round 2
// speedup vs baseline: 1.7776x; 1.7776x over previous
#include <cuda_runtime.h>
#include <math.h>
#include <stdint.h>

#define NB 16
#define NC 128
#define NL 256
#define ND 512
#define ROWS (NB*NC)   // 2048

// ---------------- scratch (no allocations allowed) ----------------
__device__ float g_E0[ROWS*ND];
__device__ float g_total[ROWS];
__device__ float g_QKV[ROWS*3*ND];
__device__ float g_ctx[ROWS*ND];
__device__ float g_R1[ROWS*ND];
__device__ float g_E1[ROWS*ND];
__device__ float g_H[ROWS*2*ND];
__device__ float g_R2[ROWS*ND];

// ---------------- masked mean pool ----------------
__global__ void pool_kernel(const float* __restrict__ x,
                            const float* __restrict__ mask) {
    const int row = blockIdx.x;
    const int tid = threadIdx.x;          // 128 threads
    __shared__ float msh[NL];
    __shared__ float red[128];

    float m0 = mask[(size_t)row*NL + tid];
    float m1 = mask[(size_t)row*NL + 128 + tid];
    msh[tid] = m0; msh[tid + 128] = m1;
    red[tid] = m0 + m1;
    __syncthreads();
    #pragma unroll
    for (int s = 64; s > 0; s >>= 1) {
        if (tid < s) red[tid] += red[tid + s];
        __syncthreads();
    }
    const float msum = red[0];

    const float4* xr = reinterpret_cast<const float4*>(x) + (size_t)row*NL*(ND/4);
    float4 acc = make_float4(0.f,0.f,0.f,0.f);
    #pragma unroll 4
    for (int l = 0; l < NL; l++) {
        float4 v = xr[(size_t)l*(ND/4) + tid];
        float m = msh[l];
        acc.x += v.x*m; acc.y += v.y*m; acc.z += v.z*m; acc.w += v.w*m;
    }
    const float inv = 1.0f / fmaxf(msum, 1.0f);
    acc.x *= inv; acc.y *= inv; acc.z *= inv; acc.w *= inv;
    reinterpret_cast<float4*>(g_E0)[(size_t)row*(ND/4) + tid] = acc;
    if (tid == 0) g_total[row] = msum;
}

// ---------------- TF32 tensor-core GEMM -------------------------------------
// C[M,N] = A[M,K] @ B[K,N] + bias (+Res) (+GELU)
// BM=128, BN=64, BK=16, 256 threads (8 warps, 4x2), warptile 32x32,
// mma.sync.m16n8k8.tf32, double-buffered smem.
#define EPI_BIAS 0
#define EPI_RES  1
#define EPI_GELU 2

__device__ __forceinline__ float gelu_exact(float v) {
    return 0.5f * v * (1.0f + erff(v * 0.70710678118654752f));
}

__device__ __forceinline__ uint32_t f2tf(float f) {
    uint32_t u;
    asm("cvt.rna.tf32.f32 %0, %1;" : "=r"(u) : "f"(f));
    return u;
}

__device__ __forceinline__ void mma_tf32(float* c, const uint32_t* a, const uint32_t* b) {
    asm volatile(
        "mma.sync.aligned.m16n8k8.row.col.f32.tf32.tf32.f32 "
        "{%0,%1,%2,%3}, {%4,%5,%6,%7}, {%8,%9}, {%0,%1,%2,%3};\n"
        : "+f"(c[0]), "+f"(c[1]), "+f"(c[2]), "+f"(c[3])
        : "r"(a[0]), "r"(a[1]), "r"(a[2]), "r"(a[3]),
          "r"(b[0]), "r"(b[1]));
}

template<int EPI>
__global__ __launch_bounds__(256)
void gemm_tc(const float* __restrict__ A, const float* __restrict__ B,
             const float* __restrict__ bias, const float* __restrict__ Res,
             float* __restrict__ C, int M, int N, int K) {
    // As stride 20: banks (20*m + k) % 32 conflict-free for frag loads.
    // Bs stride 72: banks (8*k + n) % 32 conflict-free.
    __shared__ uint32_t As[2][128][20];
    __shared__ uint32_t Bs[2][16][72];

    const int tid  = threadIdx.x;
    const int warp = tid >> 5, lane = tid & 31;
    const int gq = lane >> 2, tq = lane & 3;     // quad row / quad lane
    const int wm = (warp & 3) * 32;
    const int wn = (warp >> 2) * 32;
    const int bm0 = blockIdx.y * 128;
    const int bn0 = blockIdx.x * 64;

    // global tile load mapping
    const int arow = tid >> 2;            // 0..63 (+64)
    const int acol = (tid & 3) << 2;      // 0,4,8,12
    const int brow = tid >> 4;            // 0..15
    const int bcol = (tid & 15) << 2;     // 0..60

    const float* Ag = A + (size_t)bm0 * K;
    const float* Bg = B + bn0;

    float4 ra0 = *reinterpret_cast<const float4*>(Ag + (size_t)arow * K + acol);
    float4 ra1 = *reinterpret_cast<const float4*>(Ag + (size_t)(arow + 64) * K + acol);
    float4 rb  = *reinterpret_cast<const float4*>(Bg + (size_t)brow * N + bcol);

    *reinterpret_cast<uint4*>(&As[0][arow][acol]) =
        make_uint4(f2tf(ra0.x), f2tf(ra0.y), f2tf(ra0.z), f2tf(ra0.w));
    *reinterpret_cast<uint4*>(&As[0][arow + 64][acol]) =
        make_uint4(f2tf(ra1.x), f2tf(ra1.y), f2tf(ra1.z), f2tf(ra1.w));
    *reinterpret_cast<uint4*>(&Bs[0][brow][bcol]) =
        make_uint4(f2tf(rb.x), f2tf(rb.y), f2tf(rb.z), f2tf(rb.w));
    __syncthreads();

    float c[2][4][4];
    #pragma unroll
    for (int i = 0; i < 2; i++)
        #pragma unroll
        for (int j = 0; j < 4; j++)
            #pragma unroll
            for (int k = 0; k < 4; k++) c[i][j][k] = 0.f;

    const int ntiles = K >> 4;
    int s = 0;
    for (int kt = 0; kt < ntiles; kt++) {
        if (kt + 1 < ntiles) {
            const float* Agk = Ag + (kt + 1) * 16;
            ra0 = *reinterpret_cast<const float4*>(Agk + (size_t)arow * K + acol);
            ra1 = *reinterpret_cast<const float4*>(Agk + (size_t)(arow + 64) * K + acol);
            rb  = *reinterpret_cast<const float4*>(Bg + (size_t)((kt + 1) * 16 + brow) * N + bcol);
        }
        #pragma unroll
        for (int k0 = 0; k0 < 16; k0 += 8) {
            uint32_t af[2][4], bf[4][2];
            #pragma unroll
            for (int mt = 0; mt < 2; mt++) {
                const int r0 = wm + mt * 16 + gq;
                af[mt][0] = As[s][r0][k0 + tq];
                af[mt][1] = As[s][r0 + 8][k0 + tq];
                af[mt][2] = As[s][r0][k0 + tq + 4];
                af[mt][3] = As[s][r0 + 8][k0 + tq + 4];
            }
            #pragma unroll
            for (int nt = 0; nt < 4; nt++) {
                bf[nt][0] = Bs[s][k0 + tq][wn + nt * 8 + gq];
                bf[nt][1] = Bs[s][k0 + tq + 4][wn + nt * 8 + gq];
            }
            #pragma unroll
            for (int mt = 0; mt < 2; mt++)
                #pragma unroll
                for (int nt = 0; nt < 4; nt++)
                    mma_tf32(c[mt][nt], af[mt], bf[nt]);
        }
        if (kt + 1 < ntiles) {
            *reinterpret_cast<uint4*>(&As[s^1][arow][acol]) =
                make_uint4(f2tf(ra0.x), f2tf(ra0.y), f2tf(ra0.z), f2tf(ra0.w));
            *reinterpret_cast<uint4*>(&As[s^1][arow + 64][acol]) =
                make_uint4(f2tf(ra1.x), f2tf(ra1.y), f2tf(ra1.z), f2tf(ra1.w));
            *reinterpret_cast<uint4*>(&Bs[s^1][brow][bcol]) =
                make_uint4(f2tf(rb.x), f2tf(rb.y), f2tf(rb.z), f2tf(rb.w));
        }
        __syncthreads();
        s ^= 1;
    }

    // epilogue: c0,c1 -> (row g, col 2t/2t+1); c2,c3 -> (row g+8)
    #pragma unroll
    for (int mt = 0; mt < 2; mt++) {
        #pragma unroll
        for (int half = 0; half < 2; half++) {
            const int row = bm0 + wm + mt * 16 + gq + half * 8;
            #pragma unroll
            for (int nt = 0; nt < 4; nt++) {
                const int col = bn0 + wn + nt * 8 + 2 * tq;
                float2 r;
                r.x = c[mt][nt][half * 2 + 0];
                r.y = c[mt][nt][half * 2 + 1];
                float2 bv = *reinterpret_cast<const float2*>(bias + col);
                r.x += bv.x; r.y += bv.y;
                if (EPI == EPI_RES) {
                    float2 rv = *reinterpret_cast<const float2*>(Res + (size_t)row * N + col);
                    r.x += rv.x; r.y += rv.y;
                }
                if (EPI == EPI_GELU) {
                    r.x = gelu_exact(r.x);
                    r.y = gelu_exact(r.y);
                }
                *reinterpret_cast<float2*>(C + (size_t)row * N + col) = r;
            }
        }
    }
}

// ---------------- fused attention -------------------------------------------
__global__ __launch_bounds__(128)
void attn_kernel(const float* __restrict__ mask) {
    const int b  = blockIdx.y;
    const int c0 = blockIdx.x * 8;
    const int e  = threadIdx.x;   // 0..127

    __shared__ float q_sh[8][ND];
    __shared__ float m_sh[8][NL];
    __shared__ float A_sh[8][NC];
    __shared__ float t_sh[8];
    __shared__ float rowmax[8], rowinv[8];

    #pragma unroll
    for (int j = 0; j < 8; j++) {
        const size_t qrow = (size_t)(b*NC + c0 + j);
        float4 qv = *reinterpret_cast<const float4*>(g_QKV + qrow*3*ND + e*4);
        *reinterpret_cast<float4*>(&q_sh[j][e*4]) = qv;
        if (e < 64) {
            float4 mv = *reinterpret_cast<const float4*>(mask + qrow*NL + e*4);
            *reinterpret_cast<float4*>(&m_sh[j][e*4]) = mv;
        }
    }
    if (e < 8) t_sh[e] = g_total[b*NC + c0 + e];
    __syncthreads();

    const float* krow = g_QKV + (size_t)(b*NC + e)*3*ND + ND;
    float acc[8];
    #pragma unroll
    for (int j = 0; j < 8; j++) acc[j] = 0.f;
    for (int kk = 0; kk < ND; kk += 4) {
        float4 kv = *reinterpret_cast<const float4*>(krow + kk);
        #pragma unroll
        for (int j = 0; j < 8; j++) {
            float4 q4 = *reinterpret_cast<const float4*>(&q_sh[j][kk]);
            acc[j] += q4.x*kv.x + q4.y*kv.y + q4.z*kv.z + q4.w*kv.w;
        }
    }

    const float* mrow = mask + (size_t)(b*NC + e)*NL;
    float jacc[8];
    #pragma unroll
    for (int j = 0; j < 8; j++) jacc[j] = 0.f;
    for (int kk = 0; kk < NL; kk += 4) {
        float4 mv = *reinterpret_cast<const float4*>(mrow + kk);
        #pragma unroll
        for (int j = 0; j < 8; j++) {
            float4 m4 = *reinterpret_cast<const float4*>(&m_sh[j][kk]);
            jacc[j] += m4.x*mv.x + m4.y*mv.y + m4.z*mv.z + m4.w*mv.w;
        }
    }

    const float te = g_total[b*NC + e];
    float s[8];
    #pragma unroll
    for (int j = 0; j < 8; j++) {
        float tp = t_sh[j] + te;
        float ov = 2.0f * jacc[j] / fmaxf(tp, 1.0f);
        s[j] = acc[j] * 0.04419417382415922f * (0.5f + 0.5f * ov);
        A_sh[j][e] = s[j];
    }
    __syncthreads();

    if (e < 8) {
        float mx = -1e30f;
        for (int i = 0; i < NC; i++) mx = fmaxf(mx, A_sh[e][i]);
        float sm = 0.f;
        for (int i = 0; i < NC; i++) sm += expf(A_sh[e][i] - mx);
        rowmax[e] = mx; rowinv[e] = 1.0f / sm;
    }
    __syncthreads();

    #pragma unroll
    for (int j = 0; j < 8; j++)
        A_sh[j][e] = expf(s[j] - rowmax[j]) * rowinv[j];
    __syncthreads();

    float4 o[8];
    #pragma unroll
    for (int j = 0; j < 8; j++) o[j] = make_float4(0.f,0.f,0.f,0.f);
    for (int ee = 0; ee < NC; ee++) {
        float4 v4 = *reinterpret_cast<const float4*>(
            g_QKV + (size_t)(b*NC + ee)*3*ND + 2*ND + e*4);
        #pragma unroll
        for (int j = 0; j < 8; j++) {
            float a = A_sh[j][ee];
            o[j].x += a*v4.x; o[j].y += a*v4.y; o[j].z += a*v4.z; o[j].w += a*v4.w;
        }
    }
    #pragma unroll
    for (int j = 0; j < 8; j++) {
        *reinterpret_cast<float4*>(g_ctx + (size_t)(b*NC + c0 + j)*ND + e*4) = o[j];
    }
}

// ---------------- LayerNorm --------------------------------------------------
__global__ __launch_bounds__(128)
void ln_kernel(const float* __restrict__ R, const float* __restrict__ g,
               const float* __restrict__ be, float* __restrict__ out) {
    const int row = blockIdx.x;
    const int tid = threadIdx.x;   // 128
    __shared__ float red_s[128];
    __shared__ float red_q[128];

    float4 v = reinterpret_cast<const float4*>(R)[(size_t)row*(ND/4) + tid];
    float s  = v.x + v.y + v.z + v.w;
    float sq = v.x*v.x + v.y*v.y + v.z*v.z + v.w*v.w;
    red_s[tid] = s; red_q[tid] = sq;
    __syncthreads();
    #pragma unroll
    for (int st = 64; st > 0; st >>= 1) {
        if (tid < st) { red_s[tid] += red_s[tid+st]; red_q[tid] += red_q[tid+st]; }
        __syncthreads();
    }
    const float mean = red_s[0] * (1.0f/ND);
    const float var  = red_q[0] * (1.0f/ND) - mean*mean;
    const float inv  = rsqrtf(var + 1e-5f);

    float4 g4 = reinterpret_cast<const float4*>(g)[tid];
    float4 b4 = reinterpret_cast<const float4*>(be)[tid];
    float4 r;
    r.x = (v.x - mean)*inv*g4.x + b4.x;
    r.y = (v.y - mean)*inv*g4.y + b4.y;
    r.z = (v.z - mean)*inv*g4.z + b4.z;
    r.w = (v.w - mean)*inv*g4.w + b4.w;
    reinterpret_cast<float4*>(out)[(size_t)row*(ND/4) + tid] = r;
}

// ---------------- launch ----------------------------------------------------
extern "C" void kernel_launch(void* const* d_in, const int* in_sizes, int n_in,
                              void* d_out, int out_size) {
    const float* x    = (const float*)d_in[0];
    const float* mask = (const float*)d_in[1];
    const float* Wqkv = (const float*)d_in[2];
    const float* bqkv = (const float*)d_in[3];
    const float* Wo   = (const float*)d_in[4];
    const float* bo   = (const float*)d_in[5];
    const float* W1   = (const float*)d_in[6];
    const float* b1   = (const float*)d_in[7];
    const float* W2   = (const float*)d_in[8];
    const float* b2   = (const float*)d_in[9];
    const float* g1   = (const float*)d_in[10];
    const float* be1  = (const float*)d_in[11];
    const float* g2   = (const float*)d_in[12];
    const float* be2  = (const float*)d_in[13];
    float* out = (float*)d_out;

    float *E0, *QKV, *ctx, *R1, *E1, *H, *R2;
    cudaGetSymbolAddress((void**)&E0,  g_E0);
    cudaGetSymbolAddress((void**)&QKV, g_QKV);
    cudaGetSymbolAddress((void**)&ctx, g_ctx);
    cudaGetSymbolAddress((void**)&R1,  g_R1);
    cudaGetSymbolAddress((void**)&E1,  g_E1);
    cudaGetSymbolAddress((void**)&H,   g_H);
    cudaGetSymbolAddress((void**)&R2,  g_R2);

    // 1) masked mean pool
    pool_kernel<<<ROWS, 128>>>(x, mask);

    // 2) QKV = E0 @ Wqkv + bqkv     (2048 x 1536 x 512)
    gemm_tc<EPI_BIAS><<<dim3(3*ND/64, ROWS/128), 256>>>(E0, Wqkv, bqkv, nullptr, QKV, ROWS, 3*ND, ND);

    // 3) attention
    attn_kernel<<<dim3(NC/8, NB), 128>>>(mask);

    // 4) R1 = ctx @ Wo + bo + E0    (2048 x 512 x 512)
    gemm_tc<EPI_RES><<<dim3(ND/64, ROWS/128), 256>>>(ctx, Wo, bo, E0, R1, ROWS, ND, ND);

    // 5) E1 = LN(R1)
    ln_kernel<<<ROWS, 128>>>(R1, g1, be1, E1);

    // 6) H = gelu(E1 @ W1 + b1)     (2048 x 1024 x 512)
    gemm_tc<EPI_GELU><<<dim3(2*ND/64, ROWS/128), 256>>>(E1, W1, b1, nullptr, H, ROWS, 2*ND, ND);

    // 7) R2 = H @ W2 + b2 + E1      (2048 x 512 x 1024)
    gemm_tc<EPI_RES><<<dim3(ND/64, ROWS/128), 256>>>(H, W2, b2, E1, R2, ROWS, ND, 2*ND);

    // 8) out = LN(R2)
    ln_kernel<<<ROWS, 128>>>(R2, g2, be2, out);
}

// round 3
// speedup vs baseline: 1.9838x; 1.1160x over previous
#include <cuda_runtime.h>
#include <math.h>
#include <stdint.h>

#define NB 16
#define NC 128
#define NL 256
#define ND 512
#define ROWS (NB*NC)   // 2048

// ---------------- scratch (no allocations allowed) ----------------
__device__ float g_E0[ROWS*ND];        // fp32 (residual use)
__device__ float g_E0tf[ROWS*ND];      // tf32-rounded (GEMM A)
__device__ float g_total[ROWS];
__device__ float g_QKV[ROWS*3*ND];     // fp32
__device__ float g_ctx[ROWS*ND];       // tf32-rounded (GEMM A only)
__device__ float g_R1[ROWS*ND];
__device__ float g_E1[ROWS*ND];        // fp32 (residual)
__device__ float g_E1tf[ROWS*ND];      // tf32 (GEMM A)
__device__ float g_H[ROWS*2*ND];       // tf32-rounded (GEMM A only)
__device__ float g_R2[ROWS*ND];
__device__ float g_Wqkv[ND*3*ND];      // tf32 weights
__device__ float g_Wo[ND*ND];
__device__ float g_W1[ND*2*ND];
__device__ float g_W2[2*ND*ND];

__device__ __forceinline__ uint32_t f2tf(float f) {
    uint32_t u;
    asm("cvt.rna.tf32.f32 %0, %1;" : "=r"(u) : "f"(f));
    return u;
}
__device__ __forceinline__ float f2tf_f(float f) { return __uint_as_float(f2tf(f)); }

// ---------------- weight converter ----------------
__global__ void cvt_kernel(const float* __restrict__ in, float* __restrict__ out) {
    const int i = blockIdx.x * blockDim.x + threadIdx.x;
    float4 v = reinterpret_cast<const float4*>(in)[i];
    v.x = f2tf_f(v.x); v.y = f2tf_f(v.y); v.z = f2tf_f(v.z); v.w = f2tf_f(v.w);
    reinterpret_cast<float4*>(out)[i] = v;
}

// ---------------- masked mean pool ----------------
__global__ void pool_kernel(const float* __restrict__ x,
                            const float* __restrict__ mask) {
    const int row = blockIdx.x;
    const int tid = threadIdx.x;          // 128 threads
    __shared__ float msh[NL];
    __shared__ float red[128];

    float m0 = mask[(size_t)row*NL + tid];
    float m1 = mask[(size_t)row*NL + 128 + tid];
    msh[tid] = m0; msh[tid + 128] = m1;
    red[tid] = m0 + m1;
    __syncthreads();
    #pragma unroll
    for (int s = 64; s > 0; s >>= 1) {
        if (tid < s) red[tid] += red[tid + s];
        __syncthreads();
    }
    const float msum = red[0];

    const float4* xr = reinterpret_cast<const float4*>(x) + (size_t)row*NL*(ND/4);
    float4 acc = make_float4(0.f,0.f,0.f,0.f);
    #pragma unroll 4
    for (int l = 0; l < NL; l++) {
        float4 v = xr[(size_t)l*(ND/4) + tid];
        float m = msh[l];
        acc.x += v.x*m; acc.y += v.y*m; acc.z += v.z*m; acc.w += v.w*m;
    }
    const float inv = 1.0f / fmaxf(msum, 1.0f);
    acc.x *= inv; acc.y *= inv; acc.z *= inv; acc.w *= inv;
    reinterpret_cast<float4*>(g_E0)[(size_t)row*(ND/4) + tid] = acc;
    float4 t;
    t.x = f2tf_f(acc.x); t.y = f2tf_f(acc.y); t.z = f2tf_f(acc.z); t.w = f2tf_f(acc.w);
    reinterpret_cast<float4*>(g_E0tf)[(size_t)row*(ND/4) + tid] = t;
    if (tid == 0) g_total[row] = msum;
}

// ---------------- TF32 tensor-core GEMM, cp.async pipelined ------------------
// C[M,N] = A[M,K] @ B[K,N] + bias (+Res) (+GELU, stores tf32-rounded)
// BM=BN=64, BK=32, 128 threads (4 warps 2x2), warptile 32x32, double buffer.
#define EPI_BIAS 0
#define EPI_RES  1
#define EPI_GELU 2

__device__ __forceinline__ float gelu_exact(float v) {
    return 0.5f * v * (1.0f + erff(v * 0.70710678118654752f));
}

__device__ __forceinline__ void mma_tf32(float* c, const uint32_t* a, const uint32_t* b) {
    asm volatile(
        "mma.sync.aligned.m16n8k8.row.col.f32.tf32.tf32.f32 "
        "{%0,%1,%2,%3}, {%4,%5,%6,%7}, {%8,%9}, {%0,%1,%2,%3};\n"
        : "+f"(c[0]), "+f"(c[1]), "+f"(c[2]), "+f"(c[3])
        : "r"(a[0]), "r"(a[1]), "r"(a[2]), "r"(a[3]),
          "r"(b[0]), "r"(b[1]));
}

__device__ __forceinline__ void cp_async16(uint32_t saddr, const void* g) {
    asm volatile("cp.async.cg.shared.global [%0], [%1], 16;\n" :: "r"(saddr), "l"(g));
}
#define CP_COMMIT() asm volatile("cp.async.commit_group;\n" ::: "memory")
#define CP_WAIT0()  asm volatile("cp.async.wait_group 0;\n" ::: "memory")

#define AS_STRIDE 36
#define BS_STRIDE 72

template<int EPI>
__global__ __launch_bounds__(128)
void gemm_tc(const float* __restrict__ A, const float* __restrict__ B,
             const float* __restrict__ bias, const float* __restrict__ Res,
             float* __restrict__ C, int M, int N, int K) {
    __shared__ float As[2][64][AS_STRIDE];
    __shared__ float Bs[2][32][BS_STRIDE];

    const int tid  = threadIdx.x;
    const int warp = tid >> 5, lane = tid & 31;
    const int gq = lane >> 2, tq = lane & 3;
    const int wm = (warp & 1) * 32;
    const int wn = (warp >> 1) * 32;
    const int bm0 = blockIdx.y * 64;
    const int bn0 = blockIdx.x * 64;

    const float* Ag = A + (size_t)bm0 * K;
    const float* Bg = B + bn0;

    // per-thread copy chunk coords (4 x 16B each for A and B)
    int arow[4], acol[4], brow[4], bcol[4];
    #pragma unroll
    for (int i = 0; i < 4; i++) {
        int c = tid + i * 128;          // 0..511
        arow[i] = c >> 3;  acol[i] = (c & 7) << 2;   // 64 x 32
        brow[i] = c >> 4;  bcol[i] = (c & 15) << 2;  // 32 x 64
    }

    auto load_stage = [&](int s, int kt) {
        const float* Agk = Ag + kt * 32;
        const float* Bgk = Bg + (size_t)kt * 32 * N;
        #pragma unroll
        for (int i = 0; i < 4; i++) {
            uint32_t sa = (uint32_t)__cvta_generic_to_shared(&As[s][arow[i]][acol[i]]);
            cp_async16(sa, Agk + (size_t)arow[i] * K + acol[i]);
        }
        #pragma unroll
        for (int i = 0; i < 4; i++) {
            uint32_t sb = (uint32_t)__cvta_generic_to_shared(&Bs[s][brow[i]][bcol[i]]);
            cp_async16(sb, Bgk + (size_t)brow[i] * N + bcol[i]);
        }
    };

    float c[2][4][4];
    #pragma unroll
    for (int i = 0; i < 2; i++)
        #pragma unroll
        for (int j = 0; j < 4; j++)
            #pragma unroll
            for (int k = 0; k < 4; k++) c[i][j][k] = 0.f;

    const int ntk = K >> 5;
    load_stage(0, 0); CP_COMMIT();

    for (int kt = 0; kt < ntk; kt++) {
        CP_WAIT0();
        __syncthreads();
        if (kt + 1 < ntk) { load_stage((kt + 1) & 1, kt + 1); CP_COMMIT(); }
        const int s = kt & 1;
        #pragma unroll
        for (int k0 = 0; k0 < 32; k0 += 8) {
            uint32_t af[2][4], bf[4][2];
            #pragma unroll
            for (int mt = 0; mt < 2; mt++) {
                const int r0 = wm + mt * 16 + gq;
                af[mt][0] = __float_as_uint(As[s][r0][k0 + tq]);
                af[mt][1] = __float_as_uint(As[s][r0 + 8][k0 + tq]);
                af[mt][2] = __float_as_uint(As[s][r0][k0 + tq + 4]);
                af[mt][3] = __float_as_uint(As[s][r0 + 8][k0 + tq + 4]);
            }
            #pragma unroll
            for (int nt = 0; nt < 4; nt++) {
                bf[nt][0] = __float_as_uint(Bs[s][k0 + tq][wn + nt * 8 + gq]);
                bf[nt][1] = __float_as_uint(Bs[s][k0 + tq + 4][wn + nt * 8 + gq]);
            }
            #pragma unroll
            for (int mt = 0; mt < 2; mt++)
                #pragma unroll
                for (int nt = 0; nt < 4; nt++)
                    mma_tf32(c[mt][nt], af[mt], bf[nt]);
        }
        __syncthreads();
    }

    #pragma unroll
    for (int mt = 0; mt < 2; mt++) {
        #pragma unroll
        for (int half = 0; half < 2; half++) {
            const int row = bm0 + wm + mt * 16 + gq + half * 8;
            #pragma unroll
            for (int nt = 0; nt < 4; nt++) {
                const int col = bn0 + wn + nt * 8 + 2 * tq;
                float2 r;
                r.x = c[mt][nt][half * 2 + 0];
                r.y = c[mt][nt][half * 2 + 1];
                float2 bv = *reinterpret_cast<const float2*>(bias + col);
                r.x += bv.x; r.y += bv.y;
                if (EPI == EPI_RES) {
                    float2 rv = *reinterpret_cast<const float2*>(Res + (size_t)row * N + col);
                    r.x += rv.x; r.y += rv.y;
                }
                if (EPI == EPI_GELU) {
                    r.x = f2tf_f(gelu_exact(r.x));   // H feeds only a GEMM -> tf32
                    r.y = f2tf_f(gelu_exact(r.y));
                }
                *reinterpret_cast<float2*>(C + (size_t)row * N + col) = r;
            }
        }
    }
}

// ---------------- fused attention -------------------------------------------
__global__ __launch_bounds__(128)
void attn_kernel(const float* __restrict__ mask) {
    const int b  = blockIdx.y;
    const int c0 = blockIdx.x * 8;
    const int e  = threadIdx.x;   // 0..127

    __shared__ float q_sh[8][ND];
    __shared__ float m_sh[8][NL];
    __shared__ float A_sh[8][NC];
    __shared__ float t_sh[8];
    __shared__ float rowmax[8], rowinv[8];

    #pragma unroll
    for (int j = 0; j < 8; j++) {
        const size_t qrow = (size_t)(b*NC + c0 + j);
        float4 qv = *reinterpret_cast<const float4*>(g_QKV + qrow*3*ND + e*4);
        *reinterpret_cast<float4*>(&q_sh[j][e*4]) = qv;
        if (e < 64) {
            float4 mv = *reinterpret_cast<const float4*>(mask + qrow*NL + e*4);
            *reinterpret_cast<float4*>(&m_sh[j][e*4]) = mv;
        }
    }
    if (e < 8) t_sh[e] = g_total[b*NC + c0 + e];
    __syncthreads();

    const float* krow = g_QKV + (size_t)(b*NC + e)*3*ND + ND;
    float acc[8];
    #pragma unroll
    for (int j = 0; j < 8; j++) acc[j] = 0.f;
    for (int kk = 0; kk < ND; kk += 4) {
        float4 kv = *reinterpret_cast<const float4*>(krow + kk);
        #pragma unroll
        for (int j = 0; j < 8; j++) {
            float4 q4 = *reinterpret_cast<const float4*>(&q_sh[j][kk]);
            acc[j] += q4.x*kv.x + q4.y*kv.y + q4.z*kv.z + q4.w*kv.w;
        }
    }

    const float* mrow = mask + (size_t)(b*NC + e)*NL;
    float jacc[8];
    #pragma unroll
    for (int j = 0; j < 8; j++) jacc[j] = 0.f;
    for (int kk = 0; kk < NL; kk += 4) {
        float4 mv = *reinterpret_cast<const float4*>(mrow + kk);
        #pragma unroll
        for (int j = 0; j < 8; j++) {
            float4 m4 = *reinterpret_cast<const float4*>(&m_sh[j][kk]);
            jacc[j] += m4.x*mv.x + m4.y*mv.y + m4.z*mv.z + m4.w*mv.w;
        }
    }

    const float te = g_total[b*NC + e];
    float s[8];
    #pragma unroll
    for (int j = 0; j < 8; j++) {
        float tp = t_sh[j] + te;
        float ov = 2.0f * jacc[j] / fmaxf(tp, 1.0f);
        s[j] = acc[j] * 0.04419417382415922f * (0.5f + 0.5f * ov);
        A_sh[j][e] = s[j];
    }
    __syncthreads();

    if (e < 8) {
        float mx = -1e30f;
        for (int i = 0; i < NC; i++) mx = fmaxf(mx, A_sh[e][i]);
        float sm = 0.f;
        for (int i = 0; i < NC; i++) sm += expf(A_sh[e][i] - mx);
        rowmax[e] = mx; rowinv[e] = 1.0f / sm;
    }
    __syncthreads();

    #pragma unroll
    for (int j = 0; j < 8; j++)
        A_sh[j][e] = expf(s[j] - rowmax[j]) * rowinv[j];
    __syncthreads();

    float4 o[8];
    #pragma unroll
    for (int j = 0; j < 8; j++) o[j] = make_float4(0.f,0.f,0.f,0.f);
    for (int ee = 0; ee < NC; ee++) {
        float4 v4 = *reinterpret_cast<const float4*>(
            g_QKV + (size_t)(b*NC + ee)*3*ND + 2*ND + e*4);
        #pragma unroll
        for (int j = 0; j < 8; j++) {
            float a = A_sh[j][ee];
            o[j].x += a*v4.x; o[j].y += a*v4.y; o[j].z += a*v4.z; o[j].w += a*v4.w;
        }
    }
    #pragma unroll
    for (int j = 0; j < 8; j++) {
        float4 t;
        t.x = f2tf_f(o[j].x); t.y = f2tf_f(o[j].y);
        t.z = f2tf_f(o[j].z); t.w = f2tf_f(o[j].w);
        *reinterpret_cast<float4*>(g_ctx + (size_t)(b*NC + c0 + j)*ND + e*4) = t;
    }
}

// ---------------- LayerNorm --------------------------------------------------
template<bool WRITE_TF>
__global__ __launch_bounds__(128)
void ln_kernel(const float* __restrict__ R, const float* __restrict__ g,
               const float* __restrict__ be, float* __restrict__ out,
               float* __restrict__ out_tf) {
    const int row = blockIdx.x;
    const int tid = threadIdx.x;   // 128
    __shared__ float red_s[128];
    __shared__ float red_q[128];

    float4 v = reinterpret_cast<const float4*>(R)[(size_t)row*(ND/4) + tid];
    float s  = v.x + v.y + v.z + v.w;
    float sq = v.x*v.x + v.y*v.y + v.z*v.z + v.w*v.w;
    red_s[tid] = s; red_q[tid] = sq;
    __syncthreads();
    #pragma unroll
    for (int st = 64; st > 0; st >>= 1) {
        if (tid < st) { red_s[tid] += red_s[tid+st]; red_q[tid] += red_q[tid+st]; }
        __syncthreads();
    }
    const float mean = red_s[0] * (1.0f/ND);
    const float var  = red_q[0] * (1.0f/ND) - mean*mean;
    const float inv  = rsqrtf(var + 1e-5f);

    float4 g4 = reinterpret_cast<const float4*>(g)[tid];
    float4 b4 = reinterpret_cast<const float4*>(be)[tid];
    float4 r;
    r.x = (v.x - mean)*inv*g4.x + b4.x;
    r.y = (v.y - mean)*inv*g4.y + b4.y;
    r.z = (v.z - mean)*inv*g4.z + b4.z;
    r.w = (v.w - mean)*inv*g4.w + b4.w;
    reinterpret_cast<float4*>(out)[(size_t)row*(ND/4) + tid] = r;
    if (WRITE_TF) {
        float4 t;
        t.x = f2tf_f(r.x); t.y = f2tf_f(r.y); t.z = f2tf_f(r.z); t.w = f2tf_f(r.w);
        reinterpret_cast<float4*>(out_tf)[(size_t)row*(ND/4) + tid] = t;
    }
}

// ---------------- launch ----------------------------------------------------
extern "C" void kernel_launch(void* const* d_in, const int* in_sizes, int n_in,
                              void* d_out, int out_size) {
    const float* x    = (const float*)d_in[0];
    const float* mask = (const float*)d_in[1];
    const float* Wqkv = (const float*)d_in[2];
    const float* bqkv = (const float*)d_in[3];
    const float* Wo   = (const float*)d_in[4];
    const float* bo   = (const float*)d_in[5];
    const float* W1   = (const float*)d_in[6];
    const float* b1   = (const float*)d_in[7];
    const float* W2   = (const float*)d_in[8];
    const float* b2   = (const float*)d_in[9];
    const float* g1   = (const float*)d_in[10];
    const float* be1  = (const float*)d_in[11];
    const float* g2   = (const float*)d_in[12];
    const float* be2  = (const float*)d_in[13];
    float* out = (float*)d_out;

    float *E0, *E0tf, *QKV, *ctx, *R1, *E1, *E1tf, *H, *R2;
    float *Wqkv_tf, *Wo_tf, *W1_tf, *W2_tf;
    cudaGetSymbolAddress((void**)&E0,   g_E0);
    cudaGetSymbolAddress((void**)&E0tf, g_E0tf);
    cudaGetSymbolAddress((void**)&QKV,  g_QKV);
    cudaGetSymbolAddress((void**)&ctx,  g_ctx);
    cudaGetSymbolAddress((void**)&R1,   g_R1);
    cudaGetSymbolAddress((void**)&E1,   g_E1);
    cudaGetSymbolAddress((void**)&E1tf, g_E1tf);
    cudaGetSymbolAddress((void**)&H,    g_H);
    cudaGetSymbolAddress((void**)&R2,   g_R2);
    cudaGetSymbolAddress((void**)&Wqkv_tf, g_Wqkv);
    cudaGetSymbolAddress((void**)&Wo_tf,   g_Wo);
    cudaGetSymbolAddress((void**)&W1_tf,   g_W1);
    cudaGetSymbolAddress((void**)&W2_tf,   g_W2);

    // 0) weight tf32 conversion (rna)
    cvt_kernel<<<(ND*3*ND/4)/256, 256>>>(Wqkv, Wqkv_tf);
    cvt_kernel<<<(ND*ND/4)/256,   256>>>(Wo,   Wo_tf);
    cvt_kernel<<<(ND*2*ND/4)/256, 256>>>(W1,   W1_tf);
    cvt_kernel<<<(2*ND*ND/4)/256, 256>>>(W2,   W2_tf);

    // 1) masked mean pool (writes E0 + E0tf)
    pool_kernel<<<ROWS, 128>>>(x, mask);

    // 2) QKV = E0 @ Wqkv + bqkv     (2048 x 1536 x 512)
    gemm_tc<EPI_BIAS><<<dim3(3*ND/64, ROWS/64), 128>>>(E0tf, Wqkv_tf, bqkv, nullptr, QKV, ROWS, 3*ND, ND);

    // 3) attention (writes ctx as tf32)
    attn_kernel<<<dim3(NC/8, NB), 128>>>(mask);

    // 4) R1 = ctx @ Wo + bo + E0    (2048 x 512 x 512)
    gemm_tc<EPI_RES><<<dim3(ND/64, ROWS/64), 128>>>(ctx, Wo_tf, bo, E0, R1, ROWS, ND, ND);

    // 5) E1 = LN(R1)  (writes E1 + E1tf)
    ln_kernel<true><<<ROWS, 128>>>(R1, g1, be1, E1, E1tf);

    // 6) H = gelu(E1 @ W1 + b1)     (2048 x 1024 x 512), H stored tf32
    gemm_tc<EPI_GELU><<<dim3(2*ND/64, ROWS/64), 128>>>(E1tf, W1_tf, b1, nullptr, H, ROWS, 2*ND, ND);

    // 7) R2 = H @ W2 + b2 + E1      (2048 x 512 x 1024)
    gemm_tc<EPI_RES><<<dim3(ND/64, ROWS/64), 128>>>(H, W2_tf, b2, E1, R2, ROWS, ND, 2*ND);

    // 8) out = LN(R2)
    ln_kernel<false><<<ROWS, 128>>>(R2, g2, be2, out, nullptr);
}

// round 4
// speedup vs baseline: 2.1137x; 1.0655x over previous
#include <cuda_runtime.h>
#include <math.h>
#include <stdint.h>

#define NB 16
#define NC 128
#define NL 256
#define ND 512
#define ROWS (NB*NC)   // 2048

// ---------------- scratch (no allocations allowed) ----------------
__device__ float g_E0[ROWS*ND];        // fp32 (residual use)
__device__ float g_E0tf[ROWS*ND];      // tf32-rounded (GEMM A)
__device__ float g_total[ROWS];
__device__ float g_QKV[ROWS*3*ND];     // fp32
__device__ float g_ctx[ROWS*ND];       // tf32-rounded (GEMM A only)
__device__ float g_P[2*ROWS*ND];       // split-K partials
__device__ float g_E1[ROWS*ND];        // fp32 (residual)
__device__ float g_E1tf[ROWS*ND];      // tf32 (GEMM A)
__device__ float g_H[ROWS*2*ND];       // tf32-rounded (GEMM A only)
__device__ float g_Wqkv[ND*3*ND];      // tf32 weights
__device__ float g_Wo[ND*ND];
__device__ float g_W1[ND*2*ND];
__device__ float g_W2[2*ND*ND];

__device__ __forceinline__ uint32_t f2tf(float f) {
    uint32_t u;
    asm("cvt.rna.tf32.f32 %0, %1;" : "=r"(u) : "f"(f));
    return u;
}
__device__ __forceinline__ float f2tf_f(float f) { return __uint_as_float(f2tf(f)); }

// ---------------- fused weight converter (all 4 weights, one launch) --------
#define NW_QKV (ND*3*ND/4)             // 196608 float4
#define NW_O   (ND*ND/4)               // 65536
#define NW_1   (ND*2*ND/4)             // 131072
#define NW_2   (2*ND*ND/4)             // 131072
__global__ void cvt_all_kernel(const float* __restrict__ wqkv, const float* __restrict__ wo,
                               const float* __restrict__ w1, const float* __restrict__ w2) {
    int i = blockIdx.x * blockDim.x + threadIdx.x;
    const float4* src; float4* dst; int off;
    if (i < NW_QKV)                 { src = (const float4*)wqkv; dst = (float4*)g_Wqkv; off = i; }
    else if (i < NW_QKV+NW_O)       { src = (const float4*)wo;   dst = (float4*)g_Wo;   off = i - NW_QKV; }
    else if (i < NW_QKV+NW_O+NW_1)  { src = (const float4*)w1;   dst = (float4*)g_W1;   off = i - NW_QKV - NW_O; }
    else                            { src = (const float4*)w2;   dst = (float4*)g_W2;   off = i - NW_QKV - NW_O - NW_1; }
    float4 v = src[off];
    v.x = f2tf_f(v.x); v.y = f2tf_f(v.y); v.z = f2tf_f(v.z); v.w = f2tf_f(v.w);
    dst[off] = v;
}

// ---------------- masked mean pool ----------------
__global__ void pool_kernel(const float* __restrict__ x,
                            const float* __restrict__ mask) {
    const int row = blockIdx.x;
    const int tid = threadIdx.x;          // 128 threads
    __shared__ float msh[NL];
    __shared__ float red[128];

    float m0 = mask[(size_t)row*NL + tid];
    float m1 = mask[(size_t)row*NL + 128 + tid];
    msh[tid] = m0; msh[tid + 128] = m1;
    red[tid] = m0 + m1;
    __syncthreads();
    #pragma unroll
    for (int s = 64; s > 0; s >>= 1) {
        if (tid < s) red[tid] += red[tid + s];
        __syncthreads();
    }
    const float msum = red[0];

    const float4* xr = reinterpret_cast<const float4*>(x) + (size_t)row*NL*(ND/4);
    float4 acc = make_float4(0.f,0.f,0.f,0.f);
    #pragma unroll 8
    for (int l = 0; l < NL; l++) {
        float4 v = __ldcs(&xr[(size_t)l*(ND/4) + tid]);
        float m = msh[l];
        acc.x += v.x*m; acc.y += v.y*m; acc.z += v.z*m; acc.w += v.w*m;
    }
    const float inv = 1.0f / fmaxf(msum, 1.0f);
    acc.x *= inv; acc.y *= inv; acc.z *= inv; acc.w *= inv;
    reinterpret_cast<float4*>(g_E0)[(size_t)row*(ND/4) + tid] = acc;
    float4 t;
    t.x = f2tf_f(acc.x); t.y = f2tf_f(acc.y); t.z = f2tf_f(acc.z); t.w = f2tf_f(acc.w);
    reinterpret_cast<float4*>(g_E0tf)[(size_t)row*(ND/4) + tid] = t;
    if (tid == 0) g_total[row] = msum;
}

// ---------------- TF32 tensor-core GEMM core ---------------------------------
#define EPI_BIAS 0
#define EPI_GELU 2

__device__ __forceinline__ float gelu_exact(float v) {
    return 0.5f * v * (1.0f + erff(v * 0.70710678118654752f));
}

__device__ __forceinline__ void mma_tf32(float* c, const uint32_t* a, const uint32_t* b) {
    asm volatile(
        "mma.sync.aligned.m16n8k8.row.col.f32.tf32.tf32.f32 "
        "{%0,%1,%2,%3}, {%4,%5,%6,%7}, {%8,%9}, {%0,%1,%2,%3};\n"
        : "+f"(c[0]), "+f"(c[1]), "+f"(c[2]), "+f"(c[3])
        : "r"(a[0]), "r"(a[1]), "r"(a[2]), "r"(a[3]),
          "r"(b[0]), "r"(b[1]));
}

__device__ __forceinline__ void cp_async16(uint32_t saddr, const void* g) {
    asm volatile("cp.async.cg.shared.global [%0], [%1], 16;\n" :: "r"(saddr), "l"(g));
}
#define CP_COMMIT() asm volatile("cp.async.commit_group;\n" ::: "memory")
#define CP_WAIT0()  asm volatile("cp.async.wait_group 0;\n" ::: "memory")

#define AS_STRIDE 36
#define BS_STRIDE 72

// Shared mainloop: computes 64x64 C tile over K range, leaves accums in c[][][].
struct GemmCtx {
    int wm, wn, gq, tq;
};

template<int EPI>
__global__ __launch_bounds__(128)
void gemm_tc(const float* __restrict__ A, const float* __restrict__ B,
             const float* __restrict__ bias,
             float* __restrict__ C, int M, int N, int K) {
    __shared__ float As[2][64][AS_STRIDE];
    __shared__ float Bs[2][32][BS_STRIDE];

    const int tid  = threadIdx.x;
    const int warp = tid >> 5, lane = tid & 31;
    const int gq = lane >> 2, tq = lane & 3;
    const int wm = (warp & 1) * 32;
    const int wn = (warp >> 1) * 32;
    const int bm0 = blockIdx.y * 64;
    const int bn0 = blockIdx.x * 64;

    const float* Ag = A + (size_t)bm0 * K;
    const float* Bg = B + bn0;

    int arow[4], acol[4], brow[4], bcol[4];
    #pragma unroll
    for (int i = 0; i < 4; i++) {
        int c = tid + i * 128;
        arow[i] = c >> 3;  acol[i] = (c & 7) << 2;
        brow[i] = c >> 4;  bcol[i] = (c & 15) << 2;
    }

    auto load_stage = [&](int s, int kt) {
        const float* Agk = Ag + kt * 32;
        const float* Bgk = Bg + (size_t)kt * 32 * N;
        #pragma unroll
        for (int i = 0; i < 4; i++) {
            uint32_t sa = (uint32_t)__cvta_generic_to_shared(&As[s][arow[i]][acol[i]]);
            cp_async16(sa, Agk + (size_t)arow[i] * K + acol[i]);
        }
        #pragma unroll
        for (int i = 0; i < 4; i++) {
            uint32_t sb = (uint32_t)__cvta_generic_to_shared(&Bs[s][brow[i]][bcol[i]]);
            cp_async16(sb, Bgk + (size_t)brow[i] * N + bcol[i]);
        }
    };

    float c[2][4][4];
    #pragma unroll
    for (int i = 0; i < 2; i++)
        #pragma unroll
        for (int j = 0; j < 4; j++)
            #pragma unroll
            for (int k = 0; k < 4; k++) c[i][j][k] = 0.f;

    const int ntk = K >> 5;
    load_stage(0, 0); CP_COMMIT();

    for (int kt = 0; kt < ntk; kt++) {
        CP_WAIT0();
        __syncthreads();
        if (kt + 1 < ntk) { load_stage((kt + 1) & 1, kt + 1); CP_COMMIT(); }
        const int s = kt & 1;
        #pragma unroll
        for (int k0 = 0; k0 < 32; k0 += 8) {
            uint32_t af[2][4], bf[4][2];
            #pragma unroll
            for (int mt = 0; mt < 2; mt++) {
                const int r0 = wm + mt * 16 + gq;
                af[mt][0] = __float_as_uint(As[s][r0][k0 + tq]);
                af[mt][1] = __float_as_uint(As[s][r0 + 8][k0 + tq]);
                af[mt][2] = __float_as_uint(As[s][r0][k0 + tq + 4]);
                af[mt][3] = __float_as_uint(As[s][r0 + 8][k0 + tq + 4]);
            }
            #pragma unroll
            for (int nt = 0; nt < 4; nt++) {
                bf[nt][0] = __float_as_uint(Bs[s][k0 + tq][wn + nt * 8 + gq]);
                bf[nt][1] = __float_as_uint(Bs[s][k0 + tq + 4][wn + nt * 8 + gq]);
            }
            #pragma unroll
            for (int mt = 0; mt < 2; mt++)
                #pragma unroll
                for (int nt = 0; nt < 4; nt++)
                    mma_tf32(c[mt][nt], af[mt], bf[nt]);
        }
        __syncthreads();
    }

    #pragma unroll
    for (int mt = 0; mt < 2; mt++) {
        #pragma unroll
        for (int half = 0; half < 2; half++) {
            const int row = bm0 + wm + mt * 16 + gq + half * 8;
            #pragma unroll
            for (int nt = 0; nt < 4; nt++) {
                const int col = bn0 + wn + nt * 8 + 2 * tq;
                float2 r;
                r.x = c[mt][nt][half * 2 + 0];
                r.y = c[mt][nt][half * 2 + 1];
                float2 bv = *reinterpret_cast<const float2*>(bias + col);
                r.x += bv.x; r.y += bv.y;
                if (EPI == EPI_GELU) {
                    r.x = f2tf_f(gelu_exact(r.x));
                    r.y = f2tf_f(gelu_exact(r.y));
                }
                *reinterpret_cast<float2*>(C + (size_t)row * N + col) = r;
            }
        }
    }
}

// Split-K=2 variant: blockIdx.z selects K-half; writes raw partial (no bias).
__global__ __launch_bounds__(128)
void gemm_tc_sk(const float* __restrict__ A, const float* __restrict__ B,
                float* __restrict__ Cpart, int M, int N, int K) {
    __shared__ float As[2][64][AS_STRIDE];
    __shared__ float Bs[2][32][BS_STRIDE];

    const int tid  = threadIdx.x;
    const int warp = tid >> 5, lane = tid & 31;
    const int gq = lane >> 2, tq = lane & 3;
    const int wm = (warp & 1) * 32;
    const int wn = (warp >> 1) * 32;
    const int bm0 = blockIdx.y * 64;
    const int bn0 = blockIdx.x * 64;
    const int kz  = blockIdx.z;
    const int Kh  = K >> 1;

    const float* Ag = A + (size_t)bm0 * K + (size_t)kz * Kh;
    const float* Bg = B + bn0 + (size_t)kz * Kh * N;
    float* Cp = Cpart + (size_t)kz * M * N;

    int arow[4], acol[4], brow[4], bcol[4];
    #pragma unroll
    for (int i = 0; i < 4; i++) {
        int c = tid + i * 128;
        arow[i] = c >> 3;  acol[i] = (c & 7) << 2;
        brow[i] = c >> 4;  bcol[i] = (c & 15) << 2;
    }

    auto load_stage = [&](int s, int kt) {
        const float* Agk = Ag + kt * 32;
        const float* Bgk = Bg + (size_t)kt * 32 * N;
        #pragma unroll
        for (int i = 0; i < 4; i++) {
            uint32_t sa = (uint32_t)__cvta_generic_to_shared(&As[s][arow[i]][acol[i]]);
            cp_async16(sa, Agk + (size_t)arow[i] * K + acol[i]);
        }
        #pragma unroll
        for (int i = 0; i < 4; i++) {
            uint32_t sb = (uint32_t)__cvta_generic_to_shared(&Bs[s][brow[i]][bcol[i]]);
            cp_async16(sb, Bgk + (size_t)brow[i] * N + bcol[i]);
        }
    };

    float c[2][4][4];
    #pragma unroll
    for (int i = 0; i < 2; i++)
        #pragma unroll
        for (int j = 0; j < 4; j++)
            #pragma unroll
            for (int k = 0; k < 4; k++) c[i][j][k] = 0.f;

    const int ntk = Kh >> 5;
    load_stage(0, 0); CP_COMMIT();

    for (int kt = 0; kt < ntk; kt++) {
        CP_WAIT0();
        __syncthreads();
        if (kt + 1 < ntk) { load_stage((kt + 1) & 1, kt + 1); CP_COMMIT(); }
        const int s = kt & 1;
        #pragma unroll
        for (int k0 = 0; k0 < 32; k0 += 8) {
            uint32_t af[2][4], bf[4][2];
            #pragma unroll
            for (int mt = 0; mt < 2; mt++) {
                const int r0 = wm + mt * 16 + gq;
                af[mt][0] = __float_as_uint(As[s][r0][k0 + tq]);
                af[mt][1] = __float_as_uint(As[s][r0 + 8][k0 + tq]);
                af[mt][2] = __float_as_uint(As[s][r0][k0 + tq + 4]);
                af[mt][3] = __float_as_uint(As[s][r0 + 8][k0 + tq + 4]);
            }
            #pragma unroll
            for (int nt = 0; nt < 4; nt++) {
                bf[nt][0] = __float_as_uint(Bs[s][k0 + tq][wn + nt * 8 + gq]);
                bf[nt][1] = __float_as_uint(Bs[s][k0 + tq + 4][wn + nt * 8 + gq]);
            }
            #pragma unroll
            for (int mt = 0; mt < 2; mt++)
                #pragma unroll
                for (int nt = 0; nt < 4; nt++)
                    mma_tf32(c[mt][nt], af[mt], bf[nt]);
        }
        __syncthreads();
    }

    #pragma unroll
    for (int mt = 0; mt < 2; mt++)
        #pragma unroll
        for (int half = 0; half < 2; half++) {
            const int row = bm0 + wm + mt * 16 + gq + half * 8;
            #pragma unroll
            for (int nt = 0; nt < 4; nt++) {
                const int col = bn0 + wn + nt * 8 + 2 * tq;
                float2 r;
                r.x = c[mt][nt][half * 2 + 0];
                r.y = c[mt][nt][half * 2 + 1];
                *reinterpret_cast<float2*>(Cp + (size_t)row * N + col) = r;
            }
        }
}

// ---------------- fused attention -------------------------------------------
__global__ __launch_bounds__(128)
void attn_kernel(const float* __restrict__ mask) {
    const int b  = blockIdx.y;
    const int c0 = blockIdx.x * 8;
    const int e  = threadIdx.x;   // 0..127

    __shared__ float q_sh[8][ND];
    __shared__ float m_sh[8][NL];
    __shared__ float A_sh[8][NC];
    __shared__ float t_sh[8];
    __shared__ float rowmax[8], rowinv[8];

    #pragma unroll
    for (int j = 0; j < 8; j++) {
        const size_t qrow = (size_t)(b*NC + c0 + j);
        float4 qv = *reinterpret_cast<const float4*>(g_QKV + qrow*3*ND + e*4);
        *reinterpret_cast<float4*>(&q_sh[j][e*4]) = qv;
        if (e < 64) {
            float4 mv = *reinterpret_cast<const float4*>(mask + qrow*NL + e*4);
            *reinterpret_cast<float4*>(&m_sh[j][e*4]) = mv;
        }
    }
    if (e < 8) t_sh[e] = g_total[b*NC + c0 + e];
    __syncthreads();

    const float* krow = g_QKV + (size_t)(b*NC + e)*3*ND + ND;
    float acc[8];
    #pragma unroll
    for (int j = 0; j < 8; j++) acc[j] = 0.f;
    for (int kk = 0; kk < ND; kk += 4) {
        float4 kv = *reinterpret_cast<const float4*>(krow + kk);
        #pragma unroll
        for (int j = 0; j < 8; j++) {
            float4 q4 = *reinterpret_cast<const float4*>(&q_sh[j][kk]);
            acc[j] += q4.x*kv.x + q4.y*kv.y + q4.z*kv.z + q4.w*kv.w;
        }
    }

    const float* mrow = mask + (size_t)(b*NC + e)*NL;
    float jacc[8];
    #pragma unroll
    for (int j = 0; j < 8; j++) jacc[j] = 0.f;
    for (int kk = 0; kk < NL; kk += 4) {
        float4 mv = *reinterpret_cast<const float4*>(mrow + kk);
        #pragma unroll
        for (int j = 0; j < 8; j++) {
            float4 m4 = *reinterpret_cast<const float4*>(&m_sh[j][kk]);
            jacc[j] += m4.x*mv.x + m4.y*mv.y + m4.z*mv.z + m4.w*mv.w;
        }
    }

    const float te = g_total[b*NC + e];
    float s[8];
    #pragma unroll
    for (int j = 0; j < 8; j++) {
        float tp = t_sh[j] + te;
        float ov = 2.0f * jacc[j] / fmaxf(tp, 1.0f);
        s[j] = acc[j] * 0.04419417382415922f * (0.5f + 0.5f * ov);
        A_sh[j][e] = s[j];
    }
    __syncthreads();

    if (e < 8) {
        float mx = -1e30f;
        for (int i = 0; i < NC; i++) mx = fmaxf(mx, A_sh[e][i]);
        float sm = 0.f;
        for (int i = 0; i < NC; i++) sm += expf(A_sh[e][i] - mx);
        rowmax[e] = mx; rowinv[e] = 1.0f / sm;
    }
    __syncthreads();

    #pragma unroll
    for (int j = 0; j < 8; j++)
        A_sh[j][e] = expf(s[j] - rowmax[j]) * rowinv[j];
    __syncthreads();

    float4 o[8];
    #pragma unroll
    for (int j = 0; j < 8; j++) o[j] = make_float4(0.f,0.f,0.f,0.f);
    for (int ee = 0; ee < NC; ee++) {
        float4 v4 = *reinterpret_cast<const float4*>(
            g_QKV + (size_t)(b*NC + ee)*3*ND + 2*ND + e*4);
        #pragma unroll
        for (int j = 0; j < 8; j++) {
            float a = A_sh[j][ee];
            o[j].x += a*v4.x; o[j].y += a*v4.y; o[j].z += a*v4.z; o[j].w += a*v4.w;
        }
    }
    #pragma unroll
    for (int j = 0; j < 8; j++) {
        float4 t;
        t.x = f2tf_f(o[j].x); t.y = f2tf_f(o[j].y);
        t.z = f2tf_f(o[j].z); t.w = f2tf_f(o[j].w);
        *reinterpret_cast<float4*>(g_ctx + (size_t)(b*NC + c0 + j)*ND + e*4) = t;
    }
}

// ------------- LayerNorm combine: v = P0 + P1 + bias + Res, then LN ---------
template<bool WRITE_TF>
__global__ __launch_bounds__(128)
void ln_comb_kernel(const float* __restrict__ P,      // P0; P1 at +ROWS*ND
                    const float* __restrict__ Res,
                    const float* __restrict__ bias,
                    const float* __restrict__ g, const float* __restrict__ be,
                    float* __restrict__ out, float* __restrict__ out_tf) {
    const int row = blockIdx.x;
    const int tid = threadIdx.x;   // 128
    __shared__ float red_s[128];
    __shared__ float red_q[128];

    const size_t idx = (size_t)row*(ND/4) + tid;
    float4 p0 = reinterpret_cast<const float4*>(P)[idx];
    float4 p1 = reinterpret_cast<const float4*>(P + (size_t)ROWS*ND)[idx];
    float4 rs = reinterpret_cast<const float4*>(Res)[idx];
    float4 bb = reinterpret_cast<const float4*>(bias)[tid];
    float4 v;
    v.x = p0.x + p1.x + bb.x + rs.x;
    v.y = p0.y + p1.y + bb.y + rs.y;
    v.z = p0.z + p1.z + bb.z + rs.z;
    v.w = p0.w + p1.w + bb.w + rs.w;

    float s  = v.x + v.y + v.z + v.w;
    float sq = v.x*v.x + v.y*v.y + v.z*v.z + v.w*v.w;
    red_s[tid] = s; red_q[tid] = sq;
    __syncthreads();
    #pragma unroll
    for (int st = 64; st > 0; st >>= 1) {
        if (tid < st) { red_s[tid] += red_s[tid+st]; red_q[tid] += red_q[tid+st]; }
        __syncthreads();
    }
    const float mean = red_s[0] * (1.0f/ND);
    const float var  = red_q[0] * (1.0f/ND) - mean*mean;
    const float inv  = rsqrtf(var + 1e-5f);

    float4 g4 = reinterpret_cast<const float4*>(g)[tid];
    float4 b4 = reinterpret_cast<const float4*>(be)[tid];
    float4 r;
    r.x = (v.x - mean)*inv*g4.x + b4.x;
    r.y = (v.y - mean)*inv*g4.y + b4.y;
    r.z = (v.z - mean)*inv*g4.z + b4.z;
    r.w = (v.w - mean)*inv*g4.w + b4.w;
    reinterpret_cast<float4*>(out)[idx] = r;
    if (WRITE_TF) {
        float4 t;
        t.x = f2tf_f(r.x); t.y = f2tf_f(r.y); t.z = f2tf_f(r.z); t.w = f2tf_f(r.w);
        reinterpret_cast<float4*>(out_tf)[idx] = t;
    }
}

// ---------------- launch ----------------------------------------------------
extern "C" void kernel_launch(void* const* d_in, const int* in_sizes, int n_in,
                              void* d_out, int out_size) {
    const float* x    = (const float*)d_in[0];
    const float* mask = (const float*)d_in[1];
    const float* Wqkv = (const float*)d_in[2];
    const float* bqkv = (const float*)d_in[3];
    const float* Wo   = (const float*)d_in[4];
    const float* bo   = (const float*)d_in[5];
    const float* W1   = (const float*)d_in[6];
    const float* b1   = (const float*)d_in[7];
    const float* W2   = (const float*)d_in[8];
    const float* b2   = (const float*)d_in[9];
    const float* g1   = (const float*)d_in[10];
    const float* be1  = (const float*)d_in[11];
    const float* g2   = (const float*)d_in[12];
    const float* be2  = (const float*)d_in[13];
    float* out = (float*)d_out;

    float *E0, *E0tf, *QKV, *ctx, *P, *E1, *E1tf, *H;
    float *Wqkv_tf, *Wo_tf, *W1_tf, *W2_tf;
    cudaGetSymbolAddress((void**)&E0,   g_E0);
    cudaGetSymbolAddress((void**)&E0tf, g_E0tf);
    cudaGetSymbolAddress((void**)&QKV,  g_QKV);
    cudaGetSymbolAddress((void**)&ctx,  g_ctx);
    cudaGetSymbolAddress((void**)&P,    g_P);
    cudaGetSymbolAddress((void**)&E1,   g_E1);
    cudaGetSymbolAddress((void**)&E1tf, g_E1tf);
    cudaGetSymbolAddress((void**)&H,    g_H);
    cudaGetSymbolAddress((void**)&Wqkv_tf, g_Wqkv);
    cudaGetSymbolAddress((void**)&Wo_tf,   g_Wo);
    cudaGetSymbolAddress((void**)&W1_tf,   g_W1);
    cudaGetSymbolAddress((void**)&W2_tf,   g_W2);

    // 0) weight tf32 conversion (one fused launch)
    cvt_all_kernel<<<(NW_QKV+NW_O+NW_1+NW_2)/256, 256>>>(Wqkv, Wo, W1, W2);

    // 1) masked mean pool (writes E0 + E0tf)
    pool_kernel<<<ROWS, 128>>>(x, mask);

    // 2) QKV = E0 @ Wqkv + bqkv     (2048 x 1536 x 512)
    gemm_tc<EPI_BIAS><<<dim3(3*ND/64, ROWS/64), 128>>>(E0tf, Wqkv_tf, bqkv, QKV, ROWS, 3*ND, ND);

    // 3) attention (writes ctx as tf32)
    attn_kernel<<<dim3(NC/8, NB), 128>>>(mask);

    // 4) P = ctx @ Wo (split-K=2 partials)   (2048 x 512 x 512)
    gemm_tc_sk<<<dim3(ND/64, ROWS/64, 2), 128>>>(ctx, Wo_tf, P, ROWS, ND, ND);

    // 5) E1 = LN(P0+P1+bo+E0)  (writes E1 + E1tf)
    ln_comb_kernel<true><<<ROWS, 128>>>(P, E0, bo, g1, be1, E1, E1tf);

    // 6) H = gelu(E1 @ W1 + b1)     (2048 x 1024 x 512), H stored tf32
    gemm_tc<EPI_GELU><<<dim3(2*ND/64, ROWS/64), 128>>>(E1tf, W1_tf, b1, H, ROWS, 2*ND, ND);

    // 7) P = H @ W2 (split-K=2 partials)     (2048 x 512 x 1024)
    gemm_tc_sk<<<dim3(ND/64, ROWS/64, 2), 128>>>(H, W2_tf, P, ROWS, ND, 2*ND);

    // 8) out = LN(P0+P1+b2+E1)
    ln_comb_kernel<false><<<ROWS, 128>>>(P, E1, b2, g2, be2, out, nullptr);
}

// round 5
// speedup vs baseline: 2.2242x; 1.0523x over previous
#include <cuda_runtime.h>
#include <math.h>
#include <stdint.h>

#define NB 16
#define NC 128
#define NL 256
#define ND 512
#define ROWS (NB*NC)   // 2048

// ---------------- scratch (no allocations allowed) ----------------
__device__ float g_E0[ROWS*ND];        // fp32 (residual use)
__device__ float g_E0tf[ROWS*ND];      // tf32-rounded (GEMM A)
__device__ float g_total[ROWS];
__device__ float g_QKV[ROWS*3*ND];     // fp32
__device__ float g_ctx[ROWS*ND];       // tf32-rounded (GEMM A only)
__device__ float g_P[2*ROWS*ND];       // split-K partials
__device__ float g_E1[ROWS*ND];        // fp32 (residual)
__device__ float g_E1tf[ROWS*ND];      // tf32 (GEMM A)
__device__ float g_H[ROWS*2*ND];       // tf32-rounded (GEMM A only)
__device__ float g_Wqkv[ND*3*ND];      // tf32 weights
__device__ float g_Wo[ND*ND];
__device__ float g_W1[ND*2*ND];
__device__ float g_W2[2*ND*ND];

__device__ __forceinline__ uint32_t f2tf(float f) {
    uint32_t u;
    asm("cvt.rna.tf32.f32 %0, %1;" : "=r"(u) : "f"(f));
    return u;
}
__device__ __forceinline__ float f2tf_f(float f) { return __uint_as_float(f2tf(f)); }

// ---------------- fused weight converter (all 4 weights, one launch) --------
#define NW_QKV (ND*3*ND/4)             // 196608 float4
#define NW_O   (ND*ND/4)               // 65536
#define NW_1   (ND*2*ND/4)             // 131072
#define NW_2   (2*ND*ND/4)             // 131072
__global__ void cvt_all_kernel(const float* __restrict__ wqkv, const float* __restrict__ wo,
                               const float* __restrict__ w1, const float* __restrict__ w2) {
    int i = blockIdx.x * blockDim.x + threadIdx.x;
    const float4* src; float4* dst; int off;
    if (i < NW_QKV)                 { src = (const float4*)wqkv; dst = (float4*)g_Wqkv; off = i; }
    else if (i < NW_QKV+NW_O)       { src = (const float4*)wo;   dst = (float4*)g_Wo;   off = i - NW_QKV; }
    else if (i < NW_QKV+NW_O+NW_1)  { src = (const float4*)w1;   dst = (float4*)g_W1;   off = i - NW_QKV - NW_O; }
    else                            { src = (const float4*)w2;   dst = (float4*)g_W2;   off = i - NW_QKV - NW_O - NW_1; }
    float4 v = src[off];
    v.x = f2tf_f(v.x); v.y = f2tf_f(v.y); v.z = f2tf_f(v.z); v.w = f2tf_f(v.w);
    dst[off] = v;
}

// ---------------- masked mean pool ----------------
__global__ void pool_kernel(const float* __restrict__ x,
                            const float* __restrict__ mask) {
    const int row = blockIdx.x;
    const int tid = threadIdx.x;          // 128 threads
    __shared__ float msh[NL];
    __shared__ float red[128];

    float m0 = mask[(size_t)row*NL + tid];
    float m1 = mask[(size_t)row*NL + 128 + tid];
    msh[tid] = m0; msh[tid + 128] = m1;
    red[tid] = m0 + m1;
    __syncthreads();
    #pragma unroll
    for (int s = 64; s > 0; s >>= 1) {
        if (tid < s) red[tid] += red[tid + s];
        __syncthreads();
    }
    const float msum = red[0];

    const float4* xr = reinterpret_cast<const float4*>(x) + (size_t)row*NL*(ND/4);
    float4 acc = make_float4(0.f,0.f,0.f,0.f);
    #pragma unroll 8
    for (int l = 0; l < NL; l++) {
        float4 v = __ldcs(&xr[(size_t)l*(ND/4) + tid]);
        float m = msh[l];
        acc.x += v.x*m; acc.y += v.y*m; acc.z += v.z*m; acc.w += v.w*m;
    }
    const float inv = 1.0f / fmaxf(msum, 1.0f);
    acc.x *= inv; acc.y *= inv; acc.z *= inv; acc.w *= inv;
    reinterpret_cast<float4*>(g_E0)[(size_t)row*(ND/4) + tid] = acc;
    float4 t;
    t.x = f2tf_f(acc.x); t.y = f2tf_f(acc.y); t.z = f2tf_f(acc.z); t.w = f2tf_f(acc.w);
    reinterpret_cast<float4*>(g_E0tf)[(size_t)row*(ND/4) + tid] = t;
    if (tid == 0) g_total[row] = msum;
}

// ---------------- TF32 tensor-core GEMM core ---------------------------------
#define EPI_BIAS 0
#define EPI_GELU 2

__device__ __forceinline__ float gelu_exact(float v) {
    return 0.5f * v * (1.0f + erff(v * 0.70710678118654752f));
}

__device__ __forceinline__ void mma_tf32(float* c, const uint32_t* a, const uint32_t* b) {
    asm volatile(
        "mma.sync.aligned.m16n8k8.row.col.f32.tf32.tf32.f32 "
        "{%0,%1,%2,%3}, {%4,%5,%6,%7}, {%8,%9}, {%0,%1,%2,%3};\n"
        : "+f"(c[0]), "+f"(c[1]), "+f"(c[2]), "+f"(c[3])
        : "r"(a[0]), "r"(a[1]), "r"(a[2]), "r"(a[3]),
          "r"(b[0]), "r"(b[1]));
}

__device__ __forceinline__ void cp_async16(uint32_t saddr, const void* g) {
    asm volatile("cp.async.cg.shared.global [%0], [%1], 16;\n" :: "r"(saddr), "l"(g));
}
#define CP_COMMIT() asm volatile("cp.async.commit_group;\n" ::: "memory")
#define CP_WAIT0()  asm volatile("cp.async.wait_group 0;\n" ::: "memory")

#define AS_STRIDE 36
#define BS_STRIDE 72

template<int EPI>
__global__ __launch_bounds__(128)
void gemm_tc(const float* __restrict__ A, const float* __restrict__ B,
             const float* __restrict__ bias,
             float* __restrict__ C, int M, int N, int K) {
    __shared__ float As[2][64][AS_STRIDE];
    __shared__ float Bs[2][32][BS_STRIDE];

    const int tid  = threadIdx.x;
    const int warp = tid >> 5, lane = tid & 31;
    const int gq = lane >> 2, tq = lane & 3;
    const int wm = (warp & 1) * 32;
    const int wn = (warp >> 1) * 32;
    const int bm0 = blockIdx.y * 64;
    const int bn0 = blockIdx.x * 64;

    const float* Ag = A + (size_t)bm0 * K;
    const float* Bg = B + bn0;

    int arow[4], acol[4], brow[4], bcol[4];
    #pragma unroll
    for (int i = 0; i < 4; i++) {
        int c = tid + i * 128;
        arow[i] = c >> 3;  acol[i] = (c & 7) << 2;
        brow[i] = c >> 4;  bcol[i] = (c & 15) << 2;
    }

    auto load_stage = [&](int s, int kt) {
        const float* Agk = Ag + kt * 32;
        const float* Bgk = Bg + (size_t)kt * 32 * N;
        #pragma unroll
        for (int i = 0; i < 4; i++) {
            uint32_t sa = (uint32_t)__cvta_generic_to_shared(&As[s][arow[i]][acol[i]]);
            cp_async16(sa, Agk + (size_t)arow[i] * K + acol[i]);
        }
        #pragma unroll
        for (int i = 0; i < 4; i++) {
            uint32_t sb = (uint32_t)__cvta_generic_to_shared(&Bs[s][brow[i]][bcol[i]]);
            cp_async16(sb, Bgk + (size_t)brow[i] * N + bcol[i]);
        }
    };

    float c[2][4][4];
    #pragma unroll
    for (int i = 0; i < 2; i++)
        #pragma unroll
        for (int j = 0; j < 4; j++)
            #pragma unroll
            for (int k = 0; k < 4; k++) c[i][j][k] = 0.f;

    const int ntk = K >> 5;
    load_stage(0, 0); CP_COMMIT();

    for (int kt = 0; kt < ntk; kt++) {
        CP_WAIT0();
        __syncthreads();
        if (kt + 1 < ntk) { load_stage((kt + 1) & 1, kt + 1); CP_COMMIT(); }
        const int s = kt & 1;
        #pragma unroll
        for (int k0 = 0; k0 < 32; k0 += 8) {
            uint32_t af[2][4], bf[4][2];
            #pragma unroll
            for (int mt = 0; mt < 2; mt++) {
                const int r0 = wm + mt * 16 + gq;
                af[mt][0] = __float_as_uint(As[s][r0][k0 + tq]);
                af[mt][1] = __float_as_uint(As[s][r0 + 8][k0 + tq]);
                af[mt][2] = __float_as_uint(As[s][r0][k0 + tq + 4]);
                af[mt][3] = __float_as_uint(As[s][r0 + 8][k0 + tq + 4]);
            }
            #pragma unroll
            for (int nt = 0; nt < 4; nt++) {
                bf[nt][0] = __float_as_uint(Bs[s][k0 + tq][wn + nt * 8 + gq]);
                bf[nt][1] = __float_as_uint(Bs[s][k0 + tq + 4][wn + nt * 8 + gq]);
            }
            #pragma unroll
            for (int mt = 0; mt < 2; mt++)
                #pragma unroll
                for (int nt = 0; nt < 4; nt++)
                    mma_tf32(c[mt][nt], af[mt], bf[nt]);
        }
        __syncthreads();
    }

    #pragma unroll
    for (int mt = 0; mt < 2; mt++) {
        #pragma unroll
        for (int half = 0; half < 2; half++) {
            const int row = bm0 + wm + mt * 16 + gq + half * 8;
            #pragma unroll
            for (int nt = 0; nt < 4; nt++) {
                const int col = bn0 + wn + nt * 8 + 2 * tq;
                float2 r;
                r.x = c[mt][nt][half * 2 + 0];
                r.y = c[mt][nt][half * 2 + 1];
                float2 bv = *reinterpret_cast<const float2*>(bias + col);
                r.x += bv.x; r.y += bv.y;
                if (EPI == EPI_GELU) {
                    r.x = f2tf_f(gelu_exact(r.x));
                    r.y = f2tf_f(gelu_exact(r.y));
                }
                *reinterpret_cast<float2*>(C + (size_t)row * N + col) = r;
            }
        }
    }
}

// Split-K=2 variant: blockIdx.z selects K-half; writes raw partial (no bias).
__global__ __launch_bounds__(128)
void gemm_tc_sk(const float* __restrict__ A, const float* __restrict__ B,
                float* __restrict__ Cpart, int M, int N, int K) {
    __shared__ float As[2][64][AS_STRIDE];
    __shared__ float Bs[2][32][BS_STRIDE];

    const int tid  = threadIdx.x;
    const int warp = tid >> 5, lane = tid & 31;
    const int gq = lane >> 2, tq = lane & 3;
    const int wm = (warp & 1) * 32;
    const int wn = (warp >> 1) * 32;
    const int bm0 = blockIdx.y * 64;
    const int bn0 = blockIdx.x * 64;
    const int kz  = blockIdx.z;
    const int Kh  = K >> 1;

    const float* Ag = A + (size_t)bm0 * K + (size_t)kz * Kh;
    const float* Bg = B + bn0 + (size_t)kz * Kh * N;
    float* Cp = Cpart + (size_t)kz * M * N;

    int arow[4], acol[4], brow[4], bcol[4];
    #pragma unroll
    for (int i = 0; i < 4; i++) {
        int c = tid + i * 128;
        arow[i] = c >> 3;  acol[i] = (c & 7) << 2;
        brow[i] = c >> 4;  bcol[i] = (c & 15) << 2;
    }

    auto load_stage = [&](int s, int kt) {
        const float* Agk = Ag + kt * 32;
        const float* Bgk = Bg + (size_t)kt * 32 * N;
        #pragma unroll
        for (int i = 0; i < 4; i++) {
            uint32_t sa = (uint32_t)__cvta_generic_to_shared(&As[s][arow[i]][acol[i]]);
            cp_async16(sa, Agk + (size_t)arow[i] * K + acol[i]);
        }
        #pragma unroll
        for (int i = 0; i < 4; i++) {
            uint32_t sb = (uint32_t)__cvta_generic_to_shared(&Bs[s][brow[i]][bcol[i]]);
            cp_async16(sb, Bgk + (size_t)brow[i] * N + bcol[i]);
        }
    };

    float c[2][4][4];
    #pragma unroll
    for (int i = 0; i < 2; i++)
        #pragma unroll
        for (int j = 0; j < 4; j++)
            #pragma unroll
            for (int k = 0; k < 4; k++) c[i][j][k] = 0.f;

    const int ntk = Kh >> 5;
    load_stage(0, 0); CP_COMMIT();

    for (int kt = 0; kt < ntk; kt++) {
        CP_WAIT0();
        __syncthreads();
        if (kt + 1 < ntk) { load_stage((kt + 1) & 1, kt + 1); CP_COMMIT(); }
        const int s = kt & 1;
        #pragma unroll
        for (int k0 = 0; k0 < 32; k0 += 8) {
            uint32_t af[2][4], bf[4][2];
            #pragma unroll
            for (int mt = 0; mt < 2; mt++) {
                const int r0 = wm + mt * 16 + gq;
                af[mt][0] = __float_as_uint(As[s][r0][k0 + tq]);
                af[mt][1] = __float_as_uint(As[s][r0 + 8][k0 + tq]);
                af[mt][2] = __float_as_uint(As[s][r0][k0 + tq + 4]);
                af[mt][3] = __float_as_uint(As[s][r0 + 8][k0 + tq + 4]);
            }
            #pragma unroll
            for (int nt = 0; nt < 4; nt++) {
                bf[nt][0] = __float_as_uint(Bs[s][k0 + tq][wn + nt * 8 + gq]);
                bf[nt][1] = __float_as_uint(Bs[s][k0 + tq + 4][wn + nt * 8 + gq]);
            }
            #pragma unroll
            for (int mt = 0; mt < 2; mt++)
                #pragma unroll
                for (int nt = 0; nt < 4; nt++)
                    mma_tf32(c[mt][nt], af[mt], bf[nt]);
        }
        __syncthreads();
    }

    #pragma unroll
    for (int mt = 0; mt < 2; mt++)
        #pragma unroll
        for (int half = 0; half < 2; half++) {
            const int row = bm0 + wm + mt * 16 + gq + half * 8;
            #pragma unroll
            for (int nt = 0; nt < 4; nt++) {
                const int col = bn0 + wn + nt * 8 + 2 * tq;
                float2 r;
                r.x = c[mt][nt][half * 2 + 0];
                r.y = c[mt][nt][half * 2 + 1];
                *reinterpret_cast<float2*>(Cp + (size_t)row * N + col) = r;
            }
        }
}

// ---------------- fused attention (smem-staged, coalesced) ------------------
// grid (16 q-tiles, 16 batches), 128 threads. All K/V/mask traffic staged
// through smem with coalesced global loads; compute reads smem only.
// Dynamic smem layout (floats):
//   q_sh   [8][516]   quieries (row stride 516 keeps float4 align, bank spread)
//   m_sh   [8][260]   query masks
//   k_sh   [16][516]  K chunk (reused for V chunks in AV phase)
//   mk_sh  [16][260]  key mask chunk
//   A_sh   [8][128]   scores -> probs
//   tq_sh[8], tk_sh[128], rowmax[8], rowinv[8]
#define QS 516
#define MS 260
#define ATTN_SMEM_FLOATS (8*QS + 8*MS + 16*QS + 16*MS + 8*128 + 8 + 128 + 8 + 8)

__global__ __launch_bounds__(128)
void attn_kernel(const float* __restrict__ mask) {
    extern __shared__ float sh[];
    float* q_sh   = sh;
    float* m_sh   = q_sh  + 8*QS;
    float* k_sh   = m_sh  + 8*MS;
    float* mk_sh  = k_sh  + 16*QS;
    float* A_sh   = mk_sh + 16*MS;
    float* tq_sh  = A_sh  + 8*128;
    float* tk_sh  = tq_sh + 8;
    float* rowmax = tk_sh + 128;
    float* rowinv = rowmax + 8;

    const int b  = blockIdx.y;
    const int c0 = blockIdx.x * 8;
    const int tid = threadIdx.x;

    // load q tile (8 x 512) coalesced: 1024 float4 / 128 thr = 8 each
    #pragma unroll
    for (int i = 0; i < 8; i++) {
        int c = tid + i * 128;
        int r = c >> 7, col = (c & 127) << 2;
        float4 v = *reinterpret_cast<const float4*>(g_QKV + (size_t)(b*NC + c0 + r)*3*ND + col);
        *reinterpret_cast<float4*>(q_sh + r*QS + col) = v;
    }
    // load query masks (8 x 256): 512 float4 / 128 = 4 each
    #pragma unroll
    for (int i = 0; i < 4; i++) {
        int c = tid + i * 128;
        int r = c >> 6, col = (c & 63) << 2;
        float4 v = *reinterpret_cast<const float4*>(mask + (size_t)(b*NC + c0 + r)*NL + col);
        *reinterpret_cast<float4*>(m_sh + r*MS + col) = v;
    }
    if (tid < 8) tq_sh[tid] = g_total[b*NC + c0 + tid];
    tk_sh[tid] = g_total[b*NC + tid];
    __syncthreads();

    const int j   = tid & 7;     // query row
    const int key = tid >> 3;    // key within chunk (0..15)
    const float scale = 0.04419417382415922f;

    // scores: 8 chunks of 16 keys
    for (int ch = 0; ch < 8; ch++) {
        #pragma unroll
        for (int i = 0; i < 16; i++) {       // K chunk 16x512
            int c = tid + i * 128;
            int r = c >> 7, col = (c & 127) << 2;
            float4 v = *reinterpret_cast<const float4*>(
                g_QKV + (size_t)(b*NC + ch*16 + r)*3*ND + ND + col);
            *reinterpret_cast<float4*>(k_sh + r*QS + col) = v;
        }
        #pragma unroll
        for (int i = 0; i < 8; i++) {        // key masks 16x256
            int c = tid + i * 128;
            int r = c >> 6, col = (c & 63) << 2;
            float4 v = *reinterpret_cast<const float4*>(
                mask + (size_t)(b*NC + ch*16 + r)*NL + col);
            *reinterpret_cast<float4*>(mk_sh + r*MS + col) = v;
        }
        __syncthreads();

        const float* qr  = q_sh + j*QS;
        const float* kr  = k_sh + key*QS;
        float acc = 0.f;
        #pragma unroll 8
        for (int kk = 0; kk < ND; kk += 4) {
            float4 q4 = *reinterpret_cast<const float4*>(qr + kk);
            float4 k4 = *reinterpret_cast<const float4*>(kr + kk);
            acc += q4.x*k4.x + q4.y*k4.y + q4.z*k4.z + q4.w*k4.w;
        }
        const float* mr  = m_sh + j*MS;
        const float* mkr = mk_sh + key*MS;
        float jac = 0.f;
        #pragma unroll 8
        for (int kk = 0; kk < NL; kk += 4) {
            float4 a4 = *reinterpret_cast<const float4*>(mr + kk);
            float4 b4 = *reinterpret_cast<const float4*>(mkr + kk);
            jac += a4.x*b4.x + a4.y*b4.y + a4.z*b4.z + a4.w*b4.w;
        }
        const int kg = ch*16 + key;
        float tp = tq_sh[j] + tk_sh[kg];
        float ov = 2.0f * jac / fmaxf(tp, 1.0f);
        A_sh[j*128 + kg] = acc * scale * (0.5f + 0.5f * ov);
        __syncthreads();
    }

    // softmax
    if (tid < 8) {
        float mx = -1e30f;
        for (int i = 0; i < NC; i++) mx = fmaxf(mx, A_sh[tid*128 + i]);
        float sm = 0.f;
        for (int i = 0; i < NC; i++) sm += expf(A_sh[tid*128 + i] - mx);
        rowmax[tid] = mx; rowinv[tid] = 1.0f / sm;
    }
    __syncthreads();
    #pragma unroll
    for (int r = 0; r < 8; r++)
        A_sh[r*128 + tid] = expf(A_sh[r*128 + tid] - rowmax[r]) * rowinv[r];
    __syncthreads();

    // AV: stage V chunks into k_sh; thread owns dims [4*tid, 4*tid+4)
    float4 o[8];
    #pragma unroll
    for (int r = 0; r < 8; r++) o[r] = make_float4(0.f,0.f,0.f,0.f);
    const int d0 = tid * 4;
    for (int ch = 0; ch < 8; ch++) {
        #pragma unroll
        for (int i = 0; i < 16; i++) {
            int c = tid + i * 128;
            int r = c >> 7, col = (c & 127) << 2;
            float4 v = *reinterpret_cast<const float4*>(
                g_QKV + (size_t)(b*NC + ch*16 + r)*3*ND + 2*ND + col);
            *reinterpret_cast<float4*>(k_sh + r*QS + col) = v;
        }
        __syncthreads();
        #pragma unroll
        for (int ee = 0; ee < 16; ee++) {
            float4 v4 = *reinterpret_cast<const float4*>(k_sh + ee*QS + d0);
            const int eg = ch*16 + ee;
            #pragma unroll
            for (int r = 0; r < 8; r++) {
                float a = A_sh[r*128 + eg];
                o[r].x += a*v4.x; o[r].y += a*v4.y; o[r].z += a*v4.z; o[r].w += a*v4.w;
            }
        }
        __syncthreads();
    }

    #pragma unroll
    for (int r = 0; r < 8; r++) {
        float4 t;
        t.x = f2tf_f(o[r].x); t.y = f2tf_f(o[r].y);
        t.z = f2tf_f(o[r].z); t.w = f2tf_f(o[r].w);
        *reinterpret_cast<float4*>(g_ctx + (size_t)(b*NC + c0 + r)*ND + d0) = t;
    }
}

// ------------- LayerNorm combine: v = P0 + P1 + bias + Res, then LN ---------
template<bool WRITE_TF>
__global__ __launch_bounds__(128)
void ln_comb_kernel(const float* __restrict__ P,      // P0; P1 at +ROWS*ND
                    const float* __restrict__ Res,
                    const float* __restrict__ bias,
                    const float* __restrict__ g, const float* __restrict__ be,
                    float* __restrict__ out, float* __restrict__ out_tf) {
    const int row = blockIdx.x;
    const int tid = threadIdx.x;   // 128
    __shared__ float red_s[128];
    __shared__ float red_q[128];

    const size_t idx = (size_t)row*(ND/4) + tid;
    float4 p0 = reinterpret_cast<const float4*>(P)[idx];
    float4 p1 = reinterpret_cast<const float4*>(P + (size_t)ROWS*ND)[idx];
    float4 rs = reinterpret_cast<const float4*>(Res)[idx];
    float4 bb = reinterpret_cast<const float4*>(bias)[tid];
    float4 v;
    v.x = p0.x + p1.x + bb.x + rs.x;
    v.y = p0.y + p1.y + bb.y + rs.y;
    v.z = p0.z + p1.z + bb.z + rs.z;
    v.w = p0.w + p1.w + bb.w + rs.w;

    float s  = v.x + v.y + v.z + v.w;
    float sq = v.x*v.x + v.y*v.y + v.z*v.z + v.w*v.w;
    red_s[tid] = s; red_q[tid] = sq;
    __syncthreads();
    #pragma unroll
    for (int st = 64; st > 0; st >>= 1) {
        if (tid < st) { red_s[tid] += red_s[tid+st]; red_q[tid] += red_q[tid+st]; }
        __syncthreads();
    }
    const float mean = red_s[0] * (1.0f/ND);
    const float var  = red_q[0] * (1.0f/ND) - mean*mean;
    const float inv  = rsqrtf(var + 1e-5f);

    float4 g4 = reinterpret_cast<const float4*>(g)[tid];
    float4 b4 = reinterpret_cast<const float4*>(be)[tid];
    float4 r;
    r.x = (v.x - mean)*inv*g4.x + b4.x;
    r.y = (v.y - mean)*inv*g4.y + b4.y;
    r.z = (v.z - mean)*inv*g4.z + b4.z;
    r.w = (v.w - mean)*inv*g4.w + b4.w;
    reinterpret_cast<float4*>(out)[idx] = r;
    if (WRITE_TF) {
        float4 t;
        t.x = f2tf_f(r.x); t.y = f2tf_f(r.y); t.z = f2tf_f(r.z); t.w = f2tf_f(r.w);
        reinterpret_cast<float4*>(out_tf)[idx] = t;
    }
}

// ---------------- launch ----------------------------------------------------
extern "C" void kernel_launch(void* const* d_in, const int* in_sizes, int n_in,
                              void* d_out, int out_size) {
    const float* x    = (const float*)d_in[0];
    const float* mask = (const float*)d_in[1];
    const float* Wqkv = (const float*)d_in[2];
    const float* bqkv = (const float*)d_in[3];
    const float* Wo   = (const float*)d_in[4];
    const float* bo   = (const float*)d_in[5];
    const float* W1   = (const float*)d_in[6];
    const float* b1   = (const float*)d_in[7];
    const float* W2   = (const float*)d_in[8];
    const float* b2   = (const float*)d_in[9];
    const float* g1   = (const float*)d_in[10];
    const float* be1  = (const float*)d_in[11];
    const float* g2   = (const float*)d_in[12];
    const float* be2  = (const float*)d_in[13];
    float* out = (float*)d_out;

    float *E0, *E0tf, *QKV, *ctx, *P, *E1, *E1tf, *H;
    float *Wqkv_tf, *Wo_tf, *W1_tf, *W2_tf;
    cudaGetSymbolAddress((void**)&E0,   g_E0);
    cudaGetSymbolAddress((void**)&E0tf, g_E0tf);
    cudaGetSymbolAddress((void**)&QKV,  g_QKV);
    cudaGetSymbolAddress((void**)&ctx,  g_ctx);
    cudaGetSymbolAddress((void**)&P,    g_P);
    cudaGetSymbolAddress((void**)&E1,   g_E1);
    cudaGetSymbolAddress((void**)&E1tf, g_E1tf);
    cudaGetSymbolAddress((void**)&H,    g_H);
    cudaGetSymbolAddress((void**)&Wqkv_tf, g_Wqkv);
    cudaGetSymbolAddress((void**)&Wo_tf,   g_Wo);
    cudaGetSymbolAddress((void**)&W1_tf,   g_W1);
    cudaGetSymbolAddress((void**)&W2_tf,   g_W2);

    const int attn_smem = ATTN_SMEM_FLOATS * 4;
    cudaFuncSetAttribute(attn_kernel, cudaFuncAttributeMaxDynamicSharedMemorySize, attn_smem);

    // 0) weight tf32 conversion (one fused launch)
    cvt_all_kernel<<<(NW_QKV+NW_O+NW_1+NW_2)/256, 256>>>(Wqkv, Wo, W1, W2);

    // 1) masked mean pool (writes E0 + E0tf)
    pool_kernel<<<ROWS, 128>>>(x, mask);

    // 2) QKV = E0 @ Wqkv + bqkv     (2048 x 1536 x 512)
    gemm_tc<EPI_BIAS><<<dim3(3*ND/64, ROWS/64), 128>>>(E0tf, Wqkv_tf, bqkv, QKV, ROWS, 3*ND, ND);

    // 3) attention (writes ctx as tf32)
    attn_kernel<<<dim3(NC/8, NB), 128, attn_smem>>>(mask);

    // 4) P = ctx @ Wo (split-K=2 partials)   (2048 x 512 x 512)
    gemm_tc_sk<<<dim3(ND/64, ROWS/64, 2), 128>>>(ctx, Wo_tf, P, ROWS, ND, ND);

    // 5) E1 = LN(P0+P1+bo+E0)  (writes E1 + E1tf)
    ln_comb_kernel<true><<<ROWS, 128>>>(P, E0, bo, g1, be1, E1, E1tf);

    // 6) H = gelu(E1 @ W1 + b1)     (2048 x 1024 x 512), H stored tf32
    gemm_tc<EPI_GELU><<<dim3(2*ND/64, ROWS/64), 128>>>(E1tf, W1_tf, b1, H, ROWS, 2*ND, ND);

    // 7) P = H @ W2 (split-K=2 partials)     (2048 x 512 x 1024)
    gemm_tc_sk<<<dim3(ND/64, ROWS/64, 2), 128>>>(H, W2_tf, P, ROWS, ND, 2*ND);

    // 8) out = LN(P0+P1+b2+E1)
    ln_comb_kernel<false><<<ROWS, 128>>>(P, E1, b2, g2, be2, out, nullptr);
}

// round 6
// speedup vs baseline: 2.3566x; 1.0595x over previous
#include <cuda_runtime.h>
#include <math.h>
#include <stdint.h>

#define NB 16
#define NC 128
#define NL 256
#define ND 512
#define ROWS (NB*NC)   // 2048

// ---------------- scratch (no allocations allowed) ----------------
__device__ float g_E0[ROWS*ND];        // fp32 (residual use)
__device__ float g_E0tf[ROWS*ND];      // tf32-rounded (GEMM A)
__device__ float g_total[ROWS];
__device__ float g_QKV[ROWS*3*ND];     // fp32
__device__ float g_ctx[ROWS*ND];       // tf32-rounded (GEMM A only)
__device__ float g_P[2*ROWS*ND];       // split-K partials
__device__ float g_E1[ROWS*ND];        // fp32 (residual)
__device__ float g_E1tf[ROWS*ND];      // tf32 (GEMM A)
__device__ float g_H[ROWS*2*ND];       // tf32-rounded (GEMM A only)
__device__ float g_Wqkv[ND*3*ND];      // tf32 weights
__device__ float g_Wo[ND*ND];
__device__ float g_W1[ND*2*ND];
__device__ float g_W2[2*ND*ND];

__device__ __forceinline__ uint32_t f2tf(float f) {
    uint32_t u;
    asm("cvt.rna.tf32.f32 %0, %1;" : "=r"(u) : "f"(f));
    return u;
}
__device__ __forceinline__ float f2tf_f(float f) { return __uint_as_float(f2tf(f)); }

// ---------------- fused weight converter (all 4 weights, one launch) --------
#define NW_QKV (ND*3*ND/4)             // 196608 float4
#define NW_O   (ND*ND/4)               // 65536
#define NW_1   (ND*2*ND/4)             // 131072
#define NW_2   (2*ND*ND/4)             // 131072
__global__ void cvt_all_kernel(const float* __restrict__ wqkv, const float* __restrict__ wo,
                               const float* __restrict__ w1, const float* __restrict__ w2) {
    int i = blockIdx.x * blockDim.x + threadIdx.x;
    const float4* src; float4* dst; int off;
    if (i < NW_QKV)                 { src = (const float4*)wqkv; dst = (float4*)g_Wqkv; off = i; }
    else if (i < NW_QKV+NW_O)       { src = (const float4*)wo;   dst = (float4*)g_Wo;   off = i - NW_QKV; }
    else if (i < NW_QKV+NW_O+NW_1)  { src = (const float4*)w1;   dst = (float4*)g_W1;   off = i - NW_QKV - NW_O; }
    else                            { src = (const float4*)w2;   dst = (float4*)g_W2;   off = i - NW_QKV - NW_O - NW_1; }
    float4 v = src[off];
    v.x = f2tf_f(v.x); v.y = f2tf_f(v.y); v.z = f2tf_f(v.z); v.w = f2tf_f(v.w);
    dst[off] = v;
}

// ---------------- masked mean pool ----------------
__global__ void pool_kernel(const float* __restrict__ x,
                            const float* __restrict__ mask) {
    const int row = blockIdx.x;
    const int tid = threadIdx.x;          // 128 threads
    __shared__ float msh[NL];
    __shared__ float red[128];

    float m0 = mask[(size_t)row*NL + tid];
    float m1 = mask[(size_t)row*NL + 128 + tid];
    msh[tid] = m0; msh[tid + 128] = m1;
    red[tid] = m0 + m1;
    __syncthreads();
    #pragma unroll
    for (int s = 64; s > 0; s >>= 1) {
        if (tid < s) red[tid] += red[tid + s];
        __syncthreads();
    }
    const float msum = red[0];

    const float4* xr = reinterpret_cast<const float4*>(x) + (size_t)row*NL*(ND/4);
    float4 acc = make_float4(0.f,0.f,0.f,0.f);
    #pragma unroll 8
    for (int l = 0; l < NL; l++) {
        float4 v = __ldcs(&xr[(size_t)l*(ND/4) + tid]);
        float m = msh[l];
        acc.x += v.x*m; acc.y += v.y*m; acc.z += v.z*m; acc.w += v.w*m;
    }
    const float inv = 1.0f / fmaxf(msum, 1.0f);
    acc.x *= inv; acc.y *= inv; acc.z *= inv; acc.w *= inv;
    reinterpret_cast<float4*>(g_E0)[(size_t)row*(ND/4) + tid] = acc;
    float4 t;
    t.x = f2tf_f(acc.x); t.y = f2tf_f(acc.y); t.z = f2tf_f(acc.z); t.w = f2tf_f(acc.w);
    reinterpret_cast<float4*>(g_E0tf)[(size_t)row*(ND/4) + tid] = t;
    if (tid == 0) g_total[row] = msum;
}

// ---------------- TF32 tensor-core GEMM core ---------------------------------
#define EPI_BIAS 0
#define EPI_GELU 2

__device__ __forceinline__ float gelu_exact(float v) {
    return 0.5f * v * (1.0f + erff(v * 0.70710678118654752f));
}

__device__ __forceinline__ void mma_tf32(float* c, const uint32_t* a, const uint32_t* b) {
    asm volatile(
        "mma.sync.aligned.m16n8k8.row.col.f32.tf32.tf32.f32 "
        "{%0,%1,%2,%3}, {%4,%5,%6,%7}, {%8,%9}, {%0,%1,%2,%3};\n"
        : "+f"(c[0]), "+f"(c[1]), "+f"(c[2]), "+f"(c[3])
        : "r"(a[0]), "r"(a[1]), "r"(a[2]), "r"(a[3]),
          "r"(b[0]), "r"(b[1]));
}

__device__ __forceinline__ void cp_async16(uint32_t saddr, const void* g) {
    asm volatile("cp.async.cg.shared.global [%0], [%1], 16;\n" :: "r"(saddr), "l"(g));
}
#define CP_COMMIT() asm volatile("cp.async.commit_group;\n" ::: "memory")
#define CP_WAIT0()  asm volatile("cp.async.wait_group 0;\n" ::: "memory")

#define AS_STRIDE 36
#define BS_STRIDE 72

template<int EPI>
__global__ __launch_bounds__(128)
void gemm_tc(const float* __restrict__ A, const float* __restrict__ B,
             const float* __restrict__ bias,
             float* __restrict__ C, int M, int N, int K) {
    __shared__ float As[2][64][AS_STRIDE];
    __shared__ float Bs[2][32][BS_STRIDE];

    const int tid  = threadIdx.x;
    const int warp = tid >> 5, lane = tid & 31;
    const int gq = lane >> 2, tq = lane & 3;
    const int wm = (warp & 1) * 32;
    const int wn = (warp >> 1) * 32;
    const int bm0 = blockIdx.y * 64;
    const int bn0 = blockIdx.x * 64;

    const float* Ag = A + (size_t)bm0 * K;
    const float* Bg = B + bn0;

    int arow[4], acol[4], brow[4], bcol[4];
    #pragma unroll
    for (int i = 0; i < 4; i++) {
        int c = tid + i * 128;
        arow[i] = c >> 3;  acol[i] = (c & 7) << 2;
        brow[i] = c >> 4;  bcol[i] = (c & 15) << 2;
    }

    auto load_stage = [&](int s, int kt) {
        const float* Agk = Ag + kt * 32;
        const float* Bgk = Bg + (size_t)kt * 32 * N;
        #pragma unroll
        for (int i = 0; i < 4; i++) {
            uint32_t sa = (uint32_t)__cvta_generic_to_shared(&As[s][arow[i]][acol[i]]);
            cp_async16(sa, Agk + (size_t)arow[i] * K + acol[i]);
        }
        #pragma unroll
        for (int i = 0; i < 4; i++) {
            uint32_t sb = (uint32_t)__cvta_generic_to_shared(&Bs[s][brow[i]][bcol[i]]);
            cp_async16(sb, Bgk + (size_t)brow[i] * N + bcol[i]);
        }
    };

    float c[2][4][4];
    #pragma unroll
    for (int i = 0; i < 2; i++)
        #pragma unroll
        for (int j = 0; j < 4; j++)
            #pragma unroll
            for (int k = 0; k < 4; k++) c[i][j][k] = 0.f;

    const int ntk = K >> 5;
    load_stage(0, 0); CP_COMMIT();

    for (int kt = 0; kt < ntk; kt++) {
        CP_WAIT0();
        __syncthreads();
        if (kt + 1 < ntk) { load_stage((kt + 1) & 1, kt + 1); CP_COMMIT(); }
        const int s = kt & 1;
        #pragma unroll
        for (int k0 = 0; k0 < 32; k0 += 8) {
            uint32_t af[2][4], bf[4][2];
            #pragma unroll
            for (int mt = 0; mt < 2; mt++) {
                const int r0 = wm + mt * 16 + gq;
                af[mt][0] = __float_as_uint(As[s][r0][k0 + tq]);
                af[mt][1] = __float_as_uint(As[s][r0 + 8][k0 + tq]);
                af[mt][2] = __float_as_uint(As[s][r0][k0 + tq + 4]);
                af[mt][3] = __float_as_uint(As[s][r0 + 8][k0 + tq + 4]);
            }
            #pragma unroll
            for (int nt = 0; nt < 4; nt++) {
                bf[nt][0] = __float_as_uint(Bs[s][k0 + tq][wn + nt * 8 + gq]);
                bf[nt][1] = __float_as_uint(Bs[s][k0 + tq + 4][wn + nt * 8 + gq]);
            }
            #pragma unroll
            for (int mt = 0; mt < 2; mt++)
                #pragma unroll
                for (int nt = 0; nt < 4; nt++)
                    mma_tf32(c[mt][nt], af[mt], bf[nt]);
        }
        __syncthreads();
    }

    #pragma unroll
    for (int mt = 0; mt < 2; mt++) {
        #pragma unroll
        for (int half = 0; half < 2; half++) {
            const int row = bm0 + wm + mt * 16 + gq + half * 8;
            #pragma unroll
            for (int nt = 0; nt < 4; nt++) {
                const int col = bn0 + wn + nt * 8 + 2 * tq;
                float2 r;
                r.x = c[mt][nt][half * 2 + 0];
                r.y = c[mt][nt][half * 2 + 1];
                float2 bv = *reinterpret_cast<const float2*>(bias + col);
                r.x += bv.x; r.y += bv.y;
                if (EPI == EPI_GELU) {
                    r.x = f2tf_f(gelu_exact(r.x));
                    r.y = f2tf_f(gelu_exact(r.y));
                }
                *reinterpret_cast<float2*>(C + (size_t)row * N + col) = r;
            }
        }
    }
}

// Split-K=2 variant: blockIdx.z selects K-half; writes raw partial (no bias).
__global__ __launch_bounds__(128)
void gemm_tc_sk(const float* __restrict__ A, const float* __restrict__ B,
                float* __restrict__ Cpart, int M, int N, int K) {
    __shared__ float As[2][64][AS_STRIDE];
    __shared__ float Bs[2][32][BS_STRIDE];

    const int tid  = threadIdx.x;
    const int warp = tid >> 5, lane = tid & 31;
    const int gq = lane >> 2, tq = lane & 3;
    const int wm = (warp & 1) * 32;
    const int wn = (warp >> 1) * 32;
    const int bm0 = blockIdx.y * 64;
    const int bn0 = blockIdx.x * 64;
    const int kz  = blockIdx.z;
    const int Kh  = K >> 1;

    const float* Ag = A + (size_t)bm0 * K + (size_t)kz * Kh;
    const float* Bg = B + bn0 + (size_t)kz * Kh * N;
    float* Cp = Cpart + (size_t)kz * M * N;

    int arow[4], acol[4], brow[4], bcol[4];
    #pragma unroll
    for (int i = 0; i < 4; i++) {
        int c = tid + i * 128;
        arow[i] = c >> 3;  acol[i] = (c & 7) << 2;
        brow[i] = c >> 4;  bcol[i] = (c & 15) << 2;
    }

    auto load_stage = [&](int s, int kt) {
        const float* Agk = Ag + kt * 32;
        const float* Bgk = Bg + (size_t)kt * 32 * N;
        #pragma unroll
        for (int i = 0; i < 4; i++) {
            uint32_t sa = (uint32_t)__cvta_generic_to_shared(&As[s][arow[i]][acol[i]]);
            cp_async16(sa, Agk + (size_t)arow[i] * K + acol[i]);
        }
        #pragma unroll
        for (int i = 0; i < 4; i++) {
            uint32_t sb = (uint32_t)__cvta_generic_to_shared(&Bs[s][brow[i]][bcol[i]]);
            cp_async16(sb, Bgk + (size_t)brow[i] * N + bcol[i]);
        }
    };

    float c[2][4][4];
    #pragma unroll
    for (int i = 0; i < 2; i++)
        #pragma unroll
        for (int j = 0; j < 4; j++)
            #pragma unroll
            for (int k = 0; k < 4; k++) c[i][j][k] = 0.f;

    const int ntk = Kh >> 5;
    load_stage(0, 0); CP_COMMIT();

    for (int kt = 0; kt < ntk; kt++) {
        CP_WAIT0();
        __syncthreads();
        if (kt + 1 < ntk) { load_stage((kt + 1) & 1, kt + 1); CP_COMMIT(); }
        const int s = kt & 1;
        #pragma unroll
        for (int k0 = 0; k0 < 32; k0 += 8) {
            uint32_t af[2][4], bf[4][2];
            #pragma unroll
            for (int mt = 0; mt < 2; mt++) {
                const int r0 = wm + mt * 16 + gq;
                af[mt][0] = __float_as_uint(As[s][r0][k0 + tq]);
                af[mt][1] = __float_as_uint(As[s][r0 + 8][k0 + tq]);
                af[mt][2] = __float_as_uint(As[s][r0][k0 + tq + 4]);
                af[mt][3] = __float_as_uint(As[s][r0 + 8][k0 + tq + 4]);
            }
            #pragma unroll
            for (int nt = 0; nt < 4; nt++) {
                bf[nt][0] = __float_as_uint(Bs[s][k0 + tq][wn + nt * 8 + gq]);
                bf[nt][1] = __float_as_uint(Bs[s][k0 + tq + 4][wn + nt * 8 + gq]);
            }
            #pragma unroll
            for (int mt = 0; mt < 2; mt++)
                #pragma unroll
                for (int nt = 0; nt < 4; nt++)
                    mma_tf32(c[mt][nt], af[mt], bf[nt]);
        }
        __syncthreads();
    }

    #pragma unroll
    for (int mt = 0; mt < 2; mt++)
        #pragma unroll
        for (int half = 0; half < 2; half++) {
            const int row = bm0 + wm + mt * 16 + gq + half * 8;
            #pragma unroll
            for (int nt = 0; nt < 4; nt++) {
                const int col = bn0 + wn + nt * 8 + 2 * tq;
                float2 r;
                r.x = c[mt][nt][half * 2 + 0];
                r.y = c[mt][nt][half * 2 + 1];
                *reinterpret_cast<float2*>(Cp + (size_t)row * N + col) = r;
            }
        }
}

// ---------------- fused attention (register-tiled, LDS-lean) ----------------
// grid (16 q-tiles, 16 batches), 128 threads.
// QK/joint phase: thread = (jq in 0..1, kq in 0..3, ks in 0..15).
//   Computes 4x4 tile of dots over a 32-dim interleaved slice
//   (dims ks*4 + 64*t), then 4-step shfl_xor butterfly over the 16 slices.
#define QS 516
#define MS 260
#define ATTN_SMEM_FLOATS (8*QS + 8*MS + 16*QS + 16*MS + 8*128 + 8 + 128 + 8 + 8)

__global__ __launch_bounds__(128)
void attn_kernel(const float* __restrict__ mask) {
    extern __shared__ float sh[];
    float* q_sh   = sh;
    float* m_sh   = q_sh  + 8*QS;
    float* k_sh   = m_sh  + 8*MS;
    float* mk_sh  = k_sh  + 16*QS;
    float* A_sh   = mk_sh + 16*MS;
    float* tq_sh  = A_sh  + 8*128;
    float* tk_sh  = tq_sh + 8;
    float* rowmax = tk_sh + 128;
    float* rowinv = rowmax + 8;

    const int b  = blockIdx.y;
    const int c0 = blockIdx.x * 8;
    const int tid = threadIdx.x;

    // load q tile (8 x 512) coalesced
    #pragma unroll
    for (int i = 0; i < 8; i++) {
        int c = tid + i * 128;
        int r = c >> 7, col = (c & 127) << 2;
        float4 v = *reinterpret_cast<const float4*>(g_QKV + (size_t)(b*NC + c0 + r)*3*ND + col);
        *reinterpret_cast<float4*>(q_sh + r*QS + col) = v;
    }
    // load query masks (8 x 256)
    #pragma unroll
    for (int i = 0; i < 4; i++) {
        int c = tid + i * 128;
        int r = c >> 6, col = (c & 63) << 2;
        float4 v = *reinterpret_cast<const float4*>(mask + (size_t)(b*NC + c0 + r)*NL + col);
        *reinterpret_cast<float4*>(m_sh + r*MS + col) = v;
    }
    if (tid < 8) tq_sh[tid] = g_total[b*NC + c0 + tid];
    tk_sh[tid] = g_total[b*NC + tid];
    __syncthreads();

    // thread decomposition for QK/joint
    const int lane = tid & 31;
    const int ks   = lane & 15;                 // k-slice 0..15
    const int pos  = (tid >> 5) * 2 + (lane >> 4); // 0..7
    const int jq   = pos >> 2;                  // 0..1 (4 q-rows each)
    const int kq   = pos & 3;                   // 0..3 (4 keys each)
    const float scale = 0.04419417382415922f;

    for (int ch = 0; ch < 8; ch++) {
        #pragma unroll
        for (int i = 0; i < 16; i++) {       // K chunk 16x512
            int c = tid + i * 128;
            int r = c >> 7, col = (c & 127) << 2;
            float4 v = *reinterpret_cast<const float4*>(
                g_QKV + (size_t)(b*NC + ch*16 + r)*3*ND + ND + col);
            *reinterpret_cast<float4*>(k_sh + r*QS + col) = v;
        }
        #pragma unroll
        for (int i = 0; i < 8; i++) {        // key masks 16x256
            int c = tid + i * 128;
            int r = c >> 6, col = (c & 63) << 2;
            float4 v = *reinterpret_cast<const float4*>(
                mask + (size_t)(b*NC + ch*16 + r)*NL + col);
            *reinterpret_cast<float4*>(mk_sh + r*MS + col) = v;
        }
        __syncthreads();

        float acc[4][4], jac[4][4];
        #pragma unroll
        for (int i = 0; i < 4; i++)
            #pragma unroll
            for (int jj = 0; jj < 4; jj++) { acc[i][jj] = 0.f; jac[i][jj] = 0.f; }

        // QK over slice dims ks*4 + 64*t, t=0..7
        #pragma unroll
        for (int t = 0; t < 8; t++) {
            const int col = ks*4 + t*64;
            float4 q4[4], k4[4];
            #pragma unroll
            for (int i = 0; i < 4; i++) {
                q4[i] = *reinterpret_cast<const float4*>(q_sh + (jq*4 + i)*QS + col);
                k4[i] = *reinterpret_cast<const float4*>(k_sh + (kq*4 + i)*QS + col);
            }
            #pragma unroll
            for (int i = 0; i < 4; i++)
                #pragma unroll
                for (int jj = 0; jj < 4; jj++)
                    acc[i][jj] += q4[i].x*k4[jj].x + q4[i].y*k4[jj].y
                                + q4[i].z*k4[jj].z + q4[i].w*k4[jj].w;
        }
        // joint over slice dims ks*4 + 64*t, t=0..3 (256 dims)
        #pragma unroll
        for (int t = 0; t < 4; t++) {
            const int col = ks*4 + t*64;
            float4 a4[4], b4[4];
            #pragma unroll
            for (int i = 0; i < 4; i++) {
                a4[i] = *reinterpret_cast<const float4*>(m_sh + (jq*4 + i)*MS + col);
                b4[i] = *reinterpret_cast<const float4*>(mk_sh + (kq*4 + i)*MS + col);
            }
            #pragma unroll
            for (int i = 0; i < 4; i++)
                #pragma unroll
                for (int jj = 0; jj < 4; jj++)
                    jac[i][jj] += a4[i].x*b4[jj].x + a4[i].y*b4[jj].y
                                + a4[i].z*b4[jj].z + a4[i].w*b4[jj].w;
        }

        // butterfly-reduce across the 16 slices (lane bits 0..3)
        #pragma unroll
        for (int m = 1; m < 16; m <<= 1) {
            #pragma unroll
            for (int i = 0; i < 4; i++)
                #pragma unroll
                for (int jj = 0; jj < 4; jj++) {
                    acc[i][jj] += __shfl_xor_sync(0xffffffffu, acc[i][jj], m);
                    jac[i][jj] += __shfl_xor_sync(0xffffffffu, jac[i][jj], m);
                }
        }

        // lane ks writes element (i=ks>>2, jj=ks&3) of this thread-group's tile
        {
            const int i  = ks >> 2;
            const int jj = ks & 3;
            const int j  = jq*4 + i;
            const int kg = ch*16 + kq*4 + jj;
            float tp = tq_sh[j] + tk_sh[kg];
            float ov = 2.0f * jac[i][jj] / fmaxf(tp, 1.0f);
            A_sh[j*128 + kg] = acc[i][jj] * scale * (0.5f + 0.5f * ov);
        }
        __syncthreads();
    }

    // softmax
    if (tid < 8) {
        float mx = -1e30f;
        for (int i = 0; i < NC; i++) mx = fmaxf(mx, A_sh[tid*128 + i]);
        float sm = 0.f;
        for (int i = 0; i < NC; i++) sm += expf(A_sh[tid*128 + i] - mx);
        rowmax[tid] = mx; rowinv[tid] = 1.0f / sm;
    }
    __syncthreads();
    #pragma unroll
    for (int r = 0; r < 8; r++)
        A_sh[r*128 + tid] = expf(A_sh[r*128 + tid] - rowmax[r]) * rowinv[r];
    __syncthreads();

    // AV: stage V chunks into k_sh; thread owns dims [4*tid, 4*tid+4)
    float4 o[8];
    #pragma unroll
    for (int r = 0; r < 8; r++) o[r] = make_float4(0.f,0.f,0.f,0.f);
    const int d0 = tid * 4;
    for (int ch = 0; ch < 8; ch++) {
        #pragma unroll
        for (int i = 0; i < 16; i++) {
            int c = tid + i * 128;
            int r = c >> 7, col = (c & 127) << 2;
            float4 v = *reinterpret_cast<const float4*>(
                g_QKV + (size_t)(b*NC + ch*16 + r)*3*ND + 2*ND + col);
            *reinterpret_cast<float4*>(k_sh + r*QS + col) = v;
        }
        __syncthreads();
        #pragma unroll
        for (int ee = 0; ee < 16; ee++) {
            float4 v4 = *reinterpret_cast<const float4*>(k_sh + ee*QS + d0);
            const int eg = ch*16 + ee;
            #pragma unroll
            for (int r = 0; r < 8; r++) {
                float a = A_sh[r*128 + eg];
                o[r].x += a*v4.x; o[r].y += a*v4.y; o[r].z += a*v4.z; o[r].w += a*v4.w;
            }
        }
        __syncthreads();
    }

    #pragma unroll
    for (int r = 0; r < 8; r++) {
        float4 t;
        t.x = f2tf_f(o[r].x); t.y = f2tf_f(o[r].y);
        t.z = f2tf_f(o[r].z); t.w = f2tf_f(o[r].w);
        *reinterpret_cast<float4*>(g_ctx + (size_t)(b*NC + c0 + r)*ND + d0) = t;
    }
}

// ------------- LayerNorm combine: v = P0 + P1 + bias + Res, then LN ---------
template<bool WRITE_TF>
__global__ __launch_bounds__(128)
void ln_comb_kernel(const float* __restrict__ P,      // P0; P1 at +ROWS*ND
                    const float* __restrict__ Res,
                    const float* __restrict__ bias,
                    const float* __restrict__ g, const float* __restrict__ be,
                    float* __restrict__ out, float* __restrict__ out_tf) {
    const int row = blockIdx.x;
    const int tid = threadIdx.x;   // 128
    __shared__ float red_s[128];
    __shared__ float red_q[128];

    const size_t idx = (size_t)row*(ND/4) + tid;
    float4 p0 = reinterpret_cast<const float4*>(P)[idx];
    float4 p1 = reinterpret_cast<const float4*>(P + (size_t)ROWS*ND)[idx];
    float4 rs = reinterpret_cast<const float4*>(Res)[idx];
    float4 bb = reinterpret_cast<const float4*>(bias)[tid];
    float4 v;
    v.x = p0.x + p1.x + bb.x + rs.x;
    v.y = p0.y + p1.y + bb.y + rs.y;
    v.z = p0.z + p1.z + bb.z + rs.z;
    v.w = p0.w + p1.w + bb.w + rs.w;

    float s  = v.x + v.y + v.z + v.w;
    float sq = v.x*v.x + v.y*v.y + v.z*v.z + v.w*v.w;
    red_s[tid] = s; red_q[tid] = sq;
    __syncthreads();
    #pragma unroll
    for (int st = 64; st > 0; st >>= 1) {
        if (tid < st) { red_s[tid] += red_s[tid+st]; red_q[tid] += red_q[tid+st]; }
        __syncthreads();
    }
    const float mean = red_s[0] * (1.0f/ND);
    const float var  = red_q[0] * (1.0f/ND) - mean*mean;
    const float inv  = rsqrtf(var + 1e-5f);

    float4 g4 = reinterpret_cast<const float4*>(g)[tid];
    float4 b4 = reinterpret_cast<const float4*>(be)[tid];
    float4 r;
    r.x = (v.x - mean)*inv*g4.x + b4.x;
    r.y = (v.y - mean)*inv*g4.y + b4.y;
    r.z = (v.z - mean)*inv*g4.z + b4.z;
    r.w = (v.w - mean)*inv*g4.w + b4.w;
    reinterpret_cast<float4*>(out)[idx] = r;
    if (WRITE_TF) {
        float4 t;
        t.x = f2tf_f(r.x); t.y = f2tf_f(r.y); t.z = f2tf_f(r.z); t.w = f2tf_f(r.w);
        reinterpret_cast<float4*>(out_tf)[idx] = t;
    }
}

// ---------------- launch ----------------------------------------------------
extern "C" void kernel_launch(void* const* d_in, const int* in_sizes, int n_in,
                              void* d_out, int out_size) {
    const float* x    = (const float*)d_in[0];
    const float* mask = (const float*)d_in[1];
    const float* Wqkv = (const float*)d_in[2];
    const float* bqkv = (const float*)d_in[3];
    const float* Wo   = (const float*)d_in[4];
    const float* bo   = (const float*)d_in[5];
    const float* W1   = (const float*)d_in[6];
    const float* b1   = (const float*)d_in[7];
    const float* W2   = (const float*)d_in[8];
    const float* b2   = (const float*)d_in[9];
    const float* g1   = (const float*)d_in[10];
    const float* be1  = (const float*)d_in[11];
    const float* g2   = (const float*)d_in[12];
    const float* be2  = (const float*)d_in[13];
    float* out = (float*)d_out;

    float *E0, *E0tf, *QKV, *ctx, *P, *E1, *E1tf, *H;
    float *Wqkv_tf, *Wo_tf, *W1_tf, *W2_tf;
    cudaGetSymbolAddress((void**)&E0,   g_E0);
    cudaGetSymbolAddress((void**)&E0tf, g_E0tf);
    cudaGetSymbolAddress((void**)&QKV,  g_QKV);
    cudaGetSymbolAddress((void**)&ctx,  g_ctx);
    cudaGetSymbolAddress((void**)&P,    g_P);
    cudaGetSymbolAddress((void**)&E1,   g_E1);
    cudaGetSymbolAddress((void**)&E1tf, g_E1tf);
    cudaGetSymbolAddress((void**)&H,    g_H);
    cudaGetSymbolAddress((void**)&Wqkv_tf, g_Wqkv);
    cudaGetSymbolAddress((void**)&Wo_tf,   g_Wo);
    cudaGetSymbolAddress((void**)&W1_tf,   g_W1);
    cudaGetSymbolAddress((void**)&W2_tf,   g_W2);

    const int attn_smem = ATTN_SMEM_FLOATS * 4;
    cudaFuncSetAttribute(attn_kernel, cudaFuncAttributeMaxDynamicSharedMemorySize, attn_smem);

    // 0) weight tf32 conversion (one fused launch)
    cvt_all_kernel<<<(NW_QKV+NW_O+NW_1+NW_2)/256, 256>>>(Wqkv, Wo, W1, W2);

    // 1) masked mean pool (writes E0 + E0tf)
    pool_kernel<<<ROWS, 128>>>(x, mask);

    // 2) QKV = E0 @ Wqkv + bqkv     (2048 x 1536 x 512)
    gemm_tc<EPI_BIAS><<<dim3(3*ND/64, ROWS/64), 128>>>(E0tf, Wqkv_tf, bqkv, QKV, ROWS, 3*ND, ND);

    // 3) attention (writes ctx as tf32)
    attn_kernel<<<dim3(NC/8, NB), 128, attn_smem>>>(mask);

    // 4) P = ctx @ Wo (split-K=2 partials)   (2048 x 512 x 512)
    gemm_tc_sk<<<dim3(ND/64, ROWS/64, 2), 128>>>(ctx, Wo_tf, P, ROWS, ND, ND);

    // 5) E1 = LN(P0+P1+bo+E0)  (writes E1 + E1tf)
    ln_comb_kernel<true><<<ROWS, 128>>>(P, E0, bo, g1, be1, E1, E1tf);

    // 6) H = gelu(E1 @ W1 + b1)     (2048 x 1024 x 512), H stored tf32
    gemm_tc<EPI_GELU><<<dim3(2*ND/64, ROWS/64), 128>>>(E1tf, W1_tf, b1, H, ROWS, 2*ND, ND);

    // 7) P = H @ W2 (split-K=2 partials)     (2048 x 512 x 1024)
    gemm_tc_sk<<<dim3(ND/64, ROWS/64, 2), 128>>>(H, W2_tf, P, ROWS, ND, 2*ND);

    // 8) out = LN(P0+P1+b2+E1)
    ln_comb_kernel<false><<<ROWS, 128>>>(P, E1, b2, g2, be2, out, nullptr);
}